// round 9
// baseline (speedup 1.0000x reference)
#include <cuda_runtime.h>
#include <math.h>
#include <stdint.h>

#define Nn 20000
#define Dd 256
#define Ss 4
#define Ee 320000
#define Hh 5
#define SN (Ss * Nn)
#define QLO 252.0f

// ---------------- scratch (device globals; no allocs allowed) ----------------
__device__ float g_deg[Nn];
__device__ float g_dinv[Nn];
__device__ int   g_cnt[Nn];
__device__ int   g_rowp[Nn + 1];
__device__ int   g_fill[Nn];
__device__ int   g_csrc[Ee];
__device__ float g_cnorm[Ee];

__device__ float g_tmpW[SN * Dd];
__device__ float g_giAll[SN * 3 * Dd];
__device__ float g_gh[Nn * 3 * Dd];
__device__ float g_h1[Nn * Dd];
__device__ float g_f1[Nn * 128];
__device__ float g_f2[Nn * 64];
__device__ float g_d1[Nn * 64];

// int8 split activations: [rows, 2K] = [qhi | qlo], + per-row scale
__device__ int8_t g_xq[SN * 512];      __device__ float g_scx[SN];
__device__ int8_t g_aggq[SN * 512];    __device__ float g_scagg[SN];
__device__ int8_t g_seqq[SN * 512];    __device__ float g_scseq[SN];
__device__ int8_t g_hq[Nn * 512];      __device__ float g_schs[Nn];
__device__ int8_t g_f1q[Nn * 256];     __device__ float g_scf1[Nn];

// int8 split weights: [M, 2K] + per-row scale
__device__ int8_t g_gWq[3 * 256 * 512];  __device__ float g_scgW[3 * 256];
__device__ int8_t g_Wihq[768 * 512];     __device__ float g_scWih[768];
__device__ int8_t g_Whhq[768 * 512];     __device__ float g_scWhh[768];
__device__ int8_t g_fc1q[128 * 512];     __device__ float g_scfc1[128];
__device__ int8_t g_dh1q[64 * 512];      __device__ float g_scdh1[64];
__device__ int8_t g_fc2q[64 * 256];      __device__ float g_scfc2[64];

// ---------------- helpers ----------------
__device__ __forceinline__ void mma_s8(int* c, const uint32_t* a, const uint32_t* b) {
    asm volatile(
        "mma.sync.aligned.m16n8k32.row.col.s32.s8.s8.s32 "
        "{%0,%1,%2,%3}, {%4,%5,%6,%7}, {%8,%9}, {%0,%1,%2,%3};"
        : "+r"(c[0]), "+r"(c[1]), "+r"(c[2]), "+r"(c[3])
        : "r"(a[0]), "r"(a[1]), "r"(a[2]), "r"(a[3]), "r"(b[0]), "r"(b[1]));
}
__device__ __forceinline__ void cpa16z(uint32_t dst, const void* src, int sz) {
    asm volatile("cp.async.cg.shared.global [%0], [%1], 16, %2;"
                 :: "r"(dst), "l"(src), "r"(sz));
}
// quantize one value given row scale
__device__ __forceinline__ void quant_write(float v, float s, int8_t* hi, int8_t* lo) {
    float y = v / s;
    int qh = __float2int_rn(y);
    int ql = __float2int_rn((y - (float)qh) * QLO);
    *hi = (int8_t)qh;
    *lo = (int8_t)ql;
}

// ---------------- graph preprocessing ----------------
__global__ void k_init_deg_cnt() {
    int i = blockIdx.x * blockDim.x + threadIdx.x;
    if (i < Nn) { g_deg[i] = 1.0f; g_cnt[i] = 0; }
}
__global__ void k_edge_deg_cnt(const int* __restrict__ dst, const float* __restrict__ w) {
    int e = blockIdx.x * blockDim.x + threadIdx.x;
    if (e < Ee) {
        int t = dst[e];
        atomicAdd(&g_deg[t], w[e]);
        atomicAdd(&g_cnt[t], 1);
    }
}
__global__ void k_dinv() {
    int i = blockIdx.x * blockDim.x + threadIdx.x;
    if (i < Nn) g_dinv[i] = rsqrtf(g_deg[i]);
}
__global__ void k_scan() {
    __shared__ int wsum[32];
    __shared__ int carry_sh;
    if (threadIdx.x == 0) carry_sh = 0;
    __syncthreads();
    const int lane = threadIdx.x & 31, wid = threadIdx.x >> 5;
    const int nw = blockDim.x >> 5;
    for (int base = 0; base < Nn; base += blockDim.x) {
        int i = base + threadIdx.x;
        int v = (i < Nn) ? g_cnt[i] : 0;
        int x = v;
#pragma unroll
        for (int o = 1; o < 32; o <<= 1) {
            int y = __shfl_up_sync(0xffffffffu, x, o);
            if (lane >= o) x += y;
        }
        if (lane == 31) wsum[wid] = x;
        __syncthreads();
        if (wid == 0) {
            int s = (lane < nw) ? wsum[lane] : 0;
#pragma unroll
            for (int o = 1; o < 32; o <<= 1) {
                int y = __shfl_up_sync(0xffffffffu, s, o);
                if (lane >= o) s += y;
            }
            wsum[lane] = s;
        }
        __syncthreads();
        int warp_off = (wid == 0) ? 0 : wsum[wid - 1];
        int carry = carry_sh;
        if (i < Nn) g_rowp[i] = carry + warp_off + x - v;
        __syncthreads();
        if (threadIdx.x == blockDim.x - 1) carry_sh = carry + wsum[nw - 1];
        __syncthreads();
    }
    if (threadIdx.x == 0) g_rowp[Nn] = carry_sh;
}
__global__ void k_copy_fill() {
    int i = blockIdx.x * blockDim.x + threadIdx.x;
    if (i < Nn) g_fill[i] = g_rowp[i];
}
__global__ void k_fill_csr(const int* __restrict__ src, const int* __restrict__ dst,
                           const float* __restrict__ w) {
    int e = blockIdx.x * blockDim.x + threadIdx.x;
    if (e < Ee) {
        int s = src[e], t = dst[e];
        int pos = atomicAdd(&g_fill[t], 1);
        g_csrc[pos]  = s;
        g_cnorm[pos] = g_dinv[s] * w[e] * g_dinv[t];
    }
}

// ---------------- quantization kernels ----------------
// one block per row; blockDim == K (128 or 256)
__global__ void k_quant_rows(const float* __restrict__ in, int8_t* __restrict__ out,
                             float* __restrict__ sc, int K) {
    int row = blockIdx.x, d = threadIdx.x;
    float v = in[(size_t)row * K + d];
    __shared__ float red[8];
    __shared__ float ss;
    float m = fabsf(v);
#pragma unroll
    for (int o = 16; o; o >>= 1) m = fmaxf(m, __shfl_down_sync(0xffffffffu, m, o));
    int lane = d & 31, wd = d >> 5, nw = blockDim.x >> 5;
    if (lane == 0) red[wd] = m;
    __syncthreads();
    if (d == 0) {
        float mx = red[0];
        for (int i = 1; i < nw; i++) mx = fmaxf(mx, red[i]);
        ss = (mx > 0.f) ? mx * (1.0f / 127.0f) : 1.0f;
        sc[row] = ss;
    }
    __syncthreads();
    quant_write(v, ss, &out[(size_t)row * 2 * K + d], &out[(size_t)row * 2 * K + K + d]);
}
// transposed: in is [K, M] (GCN weight); block per output row m, blockDim == K
__global__ void k_quantT(const float* __restrict__ in, int8_t* __restrict__ out,
                         float* __restrict__ sc, int K, int M) {
    int m = blockIdx.x, d = threadIdx.x;
    float v = in[(size_t)d * M + m];
    __shared__ float red[8];
    __shared__ float ss;
    float mm = fabsf(v);
#pragma unroll
    for (int o = 16; o; o >>= 1) mm = fmaxf(mm, __shfl_down_sync(0xffffffffu, mm, o));
    int lane = d & 31, wd = d >> 5, nw = blockDim.x >> 5;
    if (lane == 0) red[wd] = mm;
    __syncthreads();
    if (d == 0) {
        float mx = red[0];
        for (int i = 1; i < nw; i++) mx = fmaxf(mx, red[i]);
        ss = (mx > 0.f) ? mx * (1.0f / 127.0f) : 1.0f;
        sc[m] = ss;
    }
    __syncthreads();
    quant_write(v, ss, &out[(size_t)m * 2 * K + d], &out[(size_t)m * 2 * K + K + d]);
}

// ---------------- int8 split IMMA GEMM ----------------
// C[R,M] = A[R,K] @ B[M,K]^T.  A/B: [rows, 2K] int8 = [qhi | qlo], row scales sA/sB.
// value = s*(qhi + qlo/252).  3 passes: hh -> acc0; hl, lh -> acc1.
// out = sA*sB*(acc0 + acc1/252) (+bias, optional exact GELU), fp32.
// Block 128x128, 512 thr, 16 warps (4M x 4N), warp 32x32. 2-stage cp.async.
#define SRI 80
__global__ void __launch_bounds__(512, 1)
gemm_i8(const int8_t* __restrict__ A, const int8_t* __restrict__ B,
        const float* __restrict__ sA, const float* __restrict__ sB,
        const float* __restrict__ bias, float* __restrict__ outF,
        int R, int M, int K, int ACT) {
    __shared__ __align__(16) int8_t sAt[2][128 * SRI];
    __shared__ __align__(16) int8_t sBt[2][128 * SRI];

    const int tid  = threadIdx.x;
    const int lane = tid & 31, wid = tid >> 5;
    const int wm = wid & 3;        // M quarter (rows)
    const int wn = wid >> 2;       // N quarter (cols)
    const long rowA = (long)blockIdx.y * 128;
    const long colB = (long)blockIdx.x * 128;
    const int K2  = 2 * K;
    const int nch = K >> 6;        // 64-byte chunks per term
    const int C   = 3 * nch;

    int acc0[2][4][4], acc1[2][4][4];
#pragma unroll
    for (int i = 0; i < 2; i++)
#pragma unroll
        for (int j = 0; j < 4; j++)
#pragma unroll
            for (int k = 0; k < 4; k++) { acc0[i][j][k] = 0; acc1[i][j][k] = 0; }

    const int ldrow = tid >> 2;          // 0..127
    const int ldseg = tid & 3;           // 0..3 (16B each)
    const long gr = rowA + ldrow;
    const long gm = colB + ldrow;
    const int8_t* aP = A + (gr < R ? gr : 0) * (long)K2 + ldseg * 16;
    const int8_t* bP = B + (gm < M ? gm : 0) * (long)K2 + ldseg * 16;
    const int aSz = (gr < R) ? 16 : 0;
    const int bSz = (gm < M) ? 16 : 0;
    const uint32_t soff = (uint32_t)(ldrow * SRI + ldseg * 16);

    auto ld_chunk = [&](int c, int buf) {
        int tt = c / nch, j = c - tt * nch;
        int ao = ((tt == 2) ? K : 0) + j * 64;   // pass2: A-lo * B-hi
        int bo = ((tt == 1) ? K : 0) + j * 64;   // pass1: A-hi * B-lo
        cpa16z((uint32_t)__cvta_generic_to_shared(&sAt[buf][0]) + soff, aP + ao, aSz);
        cpa16z((uint32_t)__cvta_generic_to_shared(&sBt[buf][0]) + soff, bP + bo, bSz);
        asm volatile("cp.async.commit_group;" ::: "memory");
    };

    ld_chunk(0, 0);

    const int aRowOff = wm * 32 + (lane >> 2);    // + mt*16 (+8 for pair)
    const int bColOff = wn * 32 + (lane >> 2);    // + nt*8
    const int kLane   = (lane & 3) * 4;

    for (int c = 0; c < C; c++) {
        int buf = c & 1;
        int tt = c / nch;
        if (c + 1 < C) {
            ld_chunk(c + 1, buf ^ 1);
            asm volatile("cp.async.wait_group 1;" ::: "memory");
        } else {
            asm volatile("cp.async.wait_group 0;" ::: "memory");
        }
        __syncthreads();

        const int8_t* baseA = &sAt[buf][0];
        const int8_t* baseB = &sBt[buf][0];
#pragma unroll
        for (int ks = 0; ks < 2; ks++) {
            uint32_t a[2][4], b[4][2];
#pragma unroll
            for (int mt = 0; mt < 2; mt++) {
                const int8_t* p = baseA + (aRowOff + mt * 16) * SRI + ks * 32 + kLane;
                a[mt][0] = *(const uint32_t*)(p);
                a[mt][1] = *(const uint32_t*)(p + 8 * SRI);
                a[mt][2] = *(const uint32_t*)(p + 16);
                a[mt][3] = *(const uint32_t*)(p + 8 * SRI + 16);
            }
#pragma unroll
            for (int nt = 0; nt < 4; nt++) {
                const int8_t* p = baseB + (bColOff + nt * 8) * SRI + ks * 32 + kLane;
                b[nt][0] = *(const uint32_t*)(p);
                b[nt][1] = *(const uint32_t*)(p + 16);
            }
            if (tt == 0) {
#pragma unroll
                for (int mt = 0; mt < 2; mt++)
#pragma unroll
                    for (int nt = 0; nt < 4; nt++)
                        mma_s8(acc0[mt][nt], a[mt], b[nt]);
            } else {
#pragma unroll
                for (int mt = 0; mt < 2; mt++)
#pragma unroll
                    for (int nt = 0; nt < 4; nt++)
                        mma_s8(acc1[mt][nt], a[mt], b[nt]);
            }
        }
        __syncthreads();
    }

    // epilogue: out = sA*sB*(acc0 + acc1/252)
#pragma unroll
    for (int mt = 0; mt < 2; mt++) {
#pragma unroll
        for (int half = 0; half < 2; half++) {
            long r = rowA + wm * 32 + mt * 16 + (lane >> 2) + half * 8;
            if (r >= R) continue;
            float sa = __ldg(sA + r);
#pragma unroll
            for (int nt = 0; nt < 4; nt++) {
#pragma unroll
                for (int cc = 0; cc < 2; cc++) {
                    int col = (int)colB + wn * 32 + nt * 8 + (lane & 3) * 2 + cc;
                    if (col >= M) continue;
                    float acc = (float)acc0[mt][nt][half * 2 + cc] +
                                (float)acc1[mt][nt][half * 2 + cc] * (1.0f / QLO);
                    float v = sa * __ldg(sB + col) * acc;
                    if (bias) v += __ldg(bias + col);
                    if (ACT) v = 0.5f * v * (1.0f + erff(v * 0.7071067811865475f));
                    outF[r * (long)M + col] = v;
                }
            }
        }
    }
}

// ---------------- batched GCN aggregate + bias + LN + ReLU -> int8 quant ----------------
__global__ void __launch_bounds__(256)
k_gcn_agg_ln_relu(const float* __restrict__ hWAll,
                  const float* __restrict__ bias, const float* __restrict__ g,
                  const float* __restrict__ b,
                  int8_t* __restrict__ outAll, float* __restrict__ scAll) {
    const int t = blockIdx.x;
    const int d = threadIdx.x;
    const float* hW = hWAll + (size_t)blockIdx.y * Nn * Dd;
    int8_t* out = outAll + (size_t)blockIdx.y * Nn * 512;
    float* sc   = scAll + (size_t)blockIdx.y * Nn;

    float di = g_dinv[t];
    float acc = di * di * hW[(size_t)t * Dd + d];
    int e0 = g_rowp[t], e1 = g_rowp[t + 1];
#pragma unroll 4
    for (int e = e0; e < e1; e++) {
        int s = __ldg(&g_csrc[e]);
        float nm = __ldg(&g_cnorm[e]);
        acc += nm * __ldg(&hW[(size_t)s * Dd + d]);
    }
    acc += bias[d];

    __shared__ float red[16];
    __shared__ float mv[3];
    float sum = acc, sq = acc * acc;
#pragma unroll
    for (int o = 16; o; o >>= 1) {
        sum += __shfl_down_sync(0xffffffffu, sum, o);
        sq  += __shfl_down_sync(0xffffffffu, sq, o);
    }
    int lane = d & 31, wid = d >> 5;
    if (lane == 0) { red[wid] = sum; red[8 + wid] = sq; }
    __syncthreads();
    if (d == 0) {
        float s = 0.f, q = 0.f;
#pragma unroll
        for (int i = 0; i < 8; i++) { s += red[i]; q += red[8 + i]; }
        float m = s * (1.0f / 256.0f);
        float var = q * (1.0f / 256.0f) - m * m;
        mv[0] = m;
        mv[1] = rsqrtf(var + 1e-5f);
    }
    __syncthreads();
    float val = fmaxf((acc - mv[0]) * mv[1] * g[d] + b[d], 0.0f);

    // row max for quantization
    float mx = val;   // val >= 0 after relu
#pragma unroll
    for (int o = 16; o; o >>= 1) mx = fmaxf(mx, __shfl_down_sync(0xffffffffu, mx, o));
    __syncthreads();
    if (lane == 0) red[wid] = mx;
    __syncthreads();
    if (d == 0) {
        float m2 = red[0];
#pragma unroll
        for (int i = 1; i < 8; i++) m2 = fmaxf(m2, red[i]);
        float s = (m2 > 0.f) ? m2 * (1.0f / 127.0f) : 1.0f;
        mv[2] = s;
        sc[t] = s;
    }
    __syncthreads();
    quant_write(val, mv[2], &out[(size_t)t * 512 + d], &out[(size_t)t * 512 + 256 + d]);
}

// ---------------- GRU cell (one block per node row) + quantize h ----------------
__global__ void __launch_bounds__(256)
k_gru_cell(const float* __restrict__ gi, const float* __restrict__ gh,
           const float* __restrict__ bhh, const float* __restrict__ hprev,
           float* __restrict__ hnew, int8_t* __restrict__ hq,
           float* __restrict__ schs, int first) {
    int n = blockIdx.x, d = threadIdx.x;
    const float* gir = gi + (size_t)n * 768;
    float ir = gir[d], iz = gir[256 + d], ig = gir[512 + d];
    float hr, hz, hg, hp;
    if (first) {
        hr = bhh[d]; hz = bhh[256 + d]; hg = bhh[512 + d]; hp = 0.f;
    } else {
        const float* ghr = gh + (size_t)n * 768;
        hr = ghr[d]; hz = ghr[256 + d]; hg = ghr[512 + d];
        hp = hprev[(size_t)n * 256 + d];
    }
    float r = 1.0f / (1.0f + expf(-(ir + hr)));
    float z = 1.0f / (1.0f + expf(-(iz + hz)));
    float ng = tanhf(ig + r * hg);
    float v = (1.0f - z) * ng + z * hp;
    hnew[(size_t)n * 256 + d] = v;

    __shared__ float red[8];
    __shared__ float ss;
    float m = fabsf(v);
#pragma unroll
    for (int o = 16; o; o >>= 1) m = fmaxf(m, __shfl_down_sync(0xffffffffu, m, o));
    int lane = d & 31, wd = d >> 5;
    if (lane == 0) red[wd] = m;
    __syncthreads();
    if (d == 0) {
        float mx = red[0];
#pragma unroll
        for (int i = 1; i < 8; i++) mx = fmaxf(mx, red[i]);
        ss = (mx > 0.f) ? mx * (1.0f / 127.0f) : 1.0f;
        schs[n] = ss;
    }
    __syncthreads();
    quant_write(v, ss, &hq[(size_t)n * 512 + d], &hq[(size_t)n * 512 + 256 + d]);
}

// ---------------- tiny head GEMM: out[N,5] = in[N,64] @ W[5,64]^T + b ----------------
__global__ void __launch_bounds__(256)
k_head5(const float* __restrict__ in, const float* __restrict__ W,
        const float* __restrict__ bias, float* __restrict__ out) {
    __shared__ float sW[5 * 64];
    for (int i = threadIdx.x; i < 5 * 64; i += blockDim.x) sW[i] = W[i];
    __syncthreads();
    int gw = (blockIdx.x * blockDim.x + threadIdx.x) >> 5;
    int lane = threadIdx.x & 31;
    if (gw >= Nn) return;
    float x0 = in[(size_t)gw * 64 + lane];
    float x1 = in[(size_t)gw * 64 + 32 + lane];
#pragma unroll
    for (int m = 0; m < 5; m++) {
        float p = x0 * sW[m * 64 + lane] + x1 * sW[m * 64 + 32 + lane];
#pragma unroll
        for (int o = 16; o; o >>= 1) p += __shfl_down_sync(0xffffffffu, p, o);
        if (lane == 0) out[(size_t)gw * 5 + m] = p + bias[m];
    }
}

// ---------------- host orchestration ----------------
template <typename T>
static T* symp(const void* sym) {
    void* p = nullptr;
    cudaGetSymbolAddress(&p, sym);
    return (T*)p;
}

extern "C" void kernel_launch(void* const* d_in, const int* in_sizes, int n_in,
                              void* d_out, int out_size) {
    const float* x    = (const float*)d_in[0];
    const int*   esrc = (const int*)d_in[1];
    const int*   edst = (const int*)d_in[2];
    const float* ew   = (const float*)d_in[3];
    const float* gcnW = (const float*)d_in[4];
    const float* gcnb = (const float*)d_in[5];
    const float* lng  = (const float*)d_in[6];
    const float* lnb  = (const float*)d_in[7];
    const float* Wih  = (const float*)d_in[8];
    const float* Whh  = (const float*)d_in[9];
    const float* bih  = (const float*)d_in[10];
    const float* bhh  = (const float*)d_in[11];
    const float* fc1W = (const float*)d_in[12];
    const float* fc1b = (const float*)d_in[13];
    const float* fc2W = (const float*)d_in[14];
    const float* fc2b = (const float*)d_in[15];
    const float* fc3W = (const float*)d_in[16];
    const float* fc3b = (const float*)d_in[17];
    const float* dh1W = (const float*)d_in[18];
    const float* dh1b = (const float*)d_in[19];
    const float* dh2W = (const float*)d_in[20];
    const float* dh2b = (const float*)d_in[21];

    float* outF = (float*)d_out;
    float* outD = outF + (size_t)Nn * Hh;

    float* tmpW  = symp<float>(g_tmpW);
    float* giAll = symp<float>(g_giAll);
    float* gh    = symp<float>(g_gh);
    float* h1    = symp<float>(g_h1);
    float* f1    = symp<float>(g_f1);
    float* f2    = symp<float>(g_f2);
    float* d1    = symp<float>(g_d1);
    int8_t* xq   = symp<int8_t>(g_xq);    float* scx   = symp<float>(g_scx);
    int8_t* aggq = symp<int8_t>(g_aggq);  float* scagg = symp<float>(g_scagg);
    int8_t* seqq = symp<int8_t>(g_seqq);  float* scseq = symp<float>(g_scseq);
    int8_t* hq   = symp<int8_t>(g_hq);    float* schs  = symp<float>(g_schs);
    int8_t* f1q  = symp<int8_t>(g_f1q);   float* scf1  = symp<float>(g_scf1);
    int8_t* gWq  = symp<int8_t>(g_gWq);   float* scgW  = symp<float>(g_scgW);
    int8_t* Wihq = symp<int8_t>(g_Wihq);  float* scWih = symp<float>(g_scWih);
    int8_t* Whhq = symp<int8_t>(g_Whhq);  float* scWhh = symp<float>(g_scWhh);
    int8_t* fc1q = symp<int8_t>(g_fc1q);  float* scfc1 = symp<float>(g_scfc1);
    int8_t* dh1q = symp<int8_t>(g_dh1q);  float* scdh1 = symp<float>(g_scdh1);
    int8_t* fc2q = symp<int8_t>(g_fc2q);  float* scfc2 = symp<float>(g_scfc2);

    const int TB = 256;
    const int gN = (Nn + TB - 1) / TB;
    const int gE = (Ee + TB - 1) / TB;

    dim3 gblk(512);
    const int RB4 = (SN + 127) / 128;   // 625
    const int RB1 = (Nn + 127) / 128;   // 157
    dim3 gGCN(2, RB4);
    dim3 gGI(6, RB4);
    dim3 gGRU(6, RB1);
    dim3 gH1(1, RB1);
    dim3 gAgg(Nn, Ss);

    // ---- prologue ordered so the big GCN GEMM stays at launch slot #4 (ncu -s 5) ----
    k_quantT<<<256, 256>>>(gcnW, gWq, scgW, 256, 256);                                  // #1
    k_quant_rows<<<SN, 256>>>(x, xq, scx, 256);                                         // #2
    k_quantT<<<256, 256>>>(gcnW + 256 * 256, gWq + (size_t)256 * 512,
                           scgW + 256, 256, 256);                                      // #3
    gemm_i8<<<gGCN, gblk>>>(xq, gWq, scx, scgW, nullptr, tmpW, SN, 256, 256, 0);        // #4 <- profile
    k_quantT<<<256, 256>>>(gcnW + 2 * 256 * 256, gWq + (size_t)512 * 512,
                           scgW + 512, 256, 256);
    k_quant_rows<<<768, 256>>>(Wih,  Wihq, scWih, 256);
    k_quant_rows<<<768, 256>>>(Whh,  Whhq, scWhh, 256);
    k_quant_rows<<<128, 256>>>(fc1W, fc1q, scfc1, 256);
    k_quant_rows<<<64, 256>>>(dh1W, dh1q, scdh1, 256);
    k_quant_rows<<<64, 128>>>(fc2W, fc2q, scfc2, 128);

    // graph preprocessing -> CSR
    k_init_deg_cnt<<<gN, TB>>>();
    k_edge_deg_cnt<<<gE, TB>>>(edst, ew);
    k_dinv<<<gN, TB>>>();
    k_scan<<<1, 1024>>>();
    k_copy_fill<<<gN, TB>>>();
    k_fill_csr<<<gE, TB>>>(esrc, edst, ew);

    // batched GCN stack (layer-0 GEMM already issued above)
    k_gcn_agg_ln_relu<<<gAgg, 256>>>(tmpW, gcnb + 0 * Dd, lng + 0 * Dd, lnb + 0 * Dd,
                                     aggq, scagg);
    gemm_i8<<<gGCN, gblk>>>(aggq, gWq + (size_t)256 * 512, scagg, scgW + 256,
                            nullptr, tmpW, SN, 256, 256, 0);
    k_gcn_agg_ln_relu<<<gAgg, 256>>>(tmpW, gcnb + 1 * Dd, lng + 1 * Dd, lnb + 1 * Dd,
                                     aggq, scagg);
    gemm_i8<<<gGCN, gblk>>>(aggq, gWq + (size_t)512 * 512, scagg, scgW + 512,
                            nullptr, tmpW, SN, 256, 256, 0);
    k_gcn_agg_ln_relu<<<gAgg, 256>>>(tmpW, gcnb + 2 * Dd, lng + 2 * Dd, lnb + 2 * Dd,
                                     seqq, scseq);

    // gi for ALL timesteps in one GEMM
    gemm_i8<<<gGI, gblk>>>(seqq, Wihq, scseq, scWih, bih, giAll, SN, 768, 256, 0);

    // GRU recurrence
    k_gru_cell<<<Nn, 256>>>(giAll, gh, bhh, h1, h1, hq, schs, 1);
    for (int t = 1; t < Ss; t++) {
        gemm_i8<<<gGRU, gblk>>>(hq, Whhq, schs, scWhh, bhh, gh, Nn, 768, 256, 0);
        k_gru_cell<<<Nn, 256>>>(giAll + (size_t)t * Nn * 768, gh, bhh, h1, h1, hq, schs, 0);
    }

    // Forecast head: 256 -> 128 (gelu) -> quant -> 64 (gelu) -> 5
    gemm_i8<<<gH1, gblk>>>(hq, fc1q, schs, scfc1, fc1b, f1, Nn, 128, 256, 1);
    k_quant_rows<<<Nn, 128>>>(f1, f1q, scf1, 128);
    gemm_i8<<<gH1, gblk>>>(f1q, fc2q, scf1, scfc2, fc2b, f2, Nn, 64, 128, 1);
    k_head5<<<(Nn * 32 + TB - 1) / TB, TB>>>(f2, fc3W, fc3b, outF);

    // Direction head: 256 -> 64 (gelu) -> 5
    gemm_i8<<<gH1, gblk>>>(hq, dh1q, schs, scdh1, dh1b, d1, Nn, 64, 256, 1);
    k_head5<<<(Nn * 32 + TB - 1) / TB, TB>>>(d1, dh2W, dh2b, outD);
}

// round 10
// speedup vs baseline: 1.9110x; 1.9110x over previous
#include <cuda_runtime.h>
#include <cuda_bf16.h>
#include <math.h>
#include <stdint.h>

#define Nn 20000
#define Dd 256
#define Ss 4
#define Ee 320000
#define Hh 5
#define SN (Ss * Nn)

// ---------------- scratch (device globals; no allocs allowed) ----------------
__device__ float g_deg[Nn];
__device__ float g_dinv[Nn];
__device__ int   g_cnt[Nn];
__device__ int   g_rowp[Nn + 1];
__device__ int   g_fill[Nn];
__device__ int   g_csrc[Ee];
__device__ float g_cnorm[Ee];

__device__ float g_tmpW[SN * Dd];
__device__ float g_giAll[SN * 3 * Dd];
__device__ float g_gh[Nn * 3 * Dd];
__device__ float g_h1[Nn * Dd];
__device__ float g_h2[Nn * Dd];
__device__ float g_f2[Nn * 64];
__device__ float g_d1[Nn * 64];
__device__ float g_cb[192];                     // fused fc1|dh1 bias

// split-bf16 activations: layout [rows, 2K] = [hi | lo]
__device__ __nv_bfloat16 g_xs[SN * 512];
__device__ __nv_bfloat16 g_aggA[SN * 512];
__device__ __nv_bfloat16 g_seqs[SN * 512];
__device__ __nv_bfloat16 g_hs[Nn * 512];
__device__ __nv_bfloat16 g_f1s[Nn * 256];

// split-bf16 weights: [M, 2K]
__device__ __nv_bfloat16 g_gcnWs[3 * 256 * 512];
__device__ __nv_bfloat16 g_Wihs[768 * 512];
__device__ __nv_bfloat16 g_Whhs[768 * 512];
__device__ __nv_bfloat16 g_cWs[192 * 512];      // fused fc1(128)|dh1(64) weights
__device__ __nv_bfloat16 g_fc2Ws[64 * 256];

// ---------------- helpers ----------------
__device__ __forceinline__ void split_write(float v, __nv_bfloat16* hi, __nv_bfloat16* lo) {
    __nv_bfloat16 h = __float2bfloat16(v);
    *hi = h;
    *lo = __float2bfloat16(v - __bfloat162float(h));
}
__device__ __forceinline__ void ldsm4(uint32_t* r, uint32_t addr) {
    asm volatile("ldmatrix.sync.aligned.m8n8.x4.shared.b16 {%0,%1,%2,%3}, [%4];"
                 : "=r"(r[0]), "=r"(r[1]), "=r"(r[2]), "=r"(r[3]) : "r"(addr));
}
__device__ __forceinline__ void mma16816(float* c, const uint32_t* a, const uint32_t* b) {
    asm volatile(
        "mma.sync.aligned.m16n8k16.row.col.f32.bf16.bf16.f32 "
        "{%0,%1,%2,%3}, {%4,%5,%6,%7}, {%8,%9}, {%0,%1,%2,%3};"
        : "+f"(c[0]), "+f"(c[1]), "+f"(c[2]), "+f"(c[3])
        : "r"(a[0]), "r"(a[1]), "r"(a[2]), "r"(a[3]), "r"(b[0]), "r"(b[1]));
}
__device__ __forceinline__ void cpa16z(uint32_t dst, const void* src, int sz) {
    asm volatile("cp.async.cg.shared.global [%0], [%1], 16, %2;"
                 :: "r"(dst), "l"(src), "r"(sz));
}

// ---------------- graph preprocessing ----------------
__global__ void k_init_deg_cnt() {
    int i = blockIdx.x * blockDim.x + threadIdx.x;
    if (i < Nn) { g_deg[i] = 1.0f; g_cnt[i] = 0; }
}
__global__ void k_edge_deg_cnt(const int* __restrict__ dst, const float* __restrict__ w) {
    int e = blockIdx.x * blockDim.x + threadIdx.x;
    if (e < Ee) {
        int t = dst[e];
        atomicAdd(&g_deg[t], w[e]);
        atomicAdd(&g_cnt[t], 1);
    }
}
__global__ void k_dinv() {
    int i = blockIdx.x * blockDim.x + threadIdx.x;
    if (i < Nn) g_dinv[i] = rsqrtf(g_deg[i]);
}
__global__ void k_scan() {
    __shared__ int wsum[32];
    __shared__ int carry_sh;
    if (threadIdx.x == 0) carry_sh = 0;
    __syncthreads();
    const int lane = threadIdx.x & 31, wid = threadIdx.x >> 5;
    const int nw = blockDim.x >> 5;
    for (int base = 0; base < Nn; base += blockDim.x) {
        int i = base + threadIdx.x;
        int v = (i < Nn) ? g_cnt[i] : 0;
        int x = v;
#pragma unroll
        for (int o = 1; o < 32; o <<= 1) {
            int y = __shfl_up_sync(0xffffffffu, x, o);
            if (lane >= o) x += y;
        }
        if (lane == 31) wsum[wid] = x;
        __syncthreads();
        if (wid == 0) {
            int s = (lane < nw) ? wsum[lane] : 0;
#pragma unroll
            for (int o = 1; o < 32; o <<= 1) {
                int y = __shfl_up_sync(0xffffffffu, s, o);
                if (lane >= o) s += y;
            }
            wsum[lane] = s;
        }
        __syncthreads();
        int warp_off = (wid == 0) ? 0 : wsum[wid - 1];
        int carry = carry_sh;
        if (i < Nn) g_rowp[i] = carry + warp_off + x - v;
        __syncthreads();
        if (threadIdx.x == blockDim.x - 1) carry_sh = carry + wsum[nw - 1];
        __syncthreads();
    }
    if (threadIdx.x == 0) g_rowp[Nn] = carry_sh;
}
__global__ void k_copy_fill() {
    int i = blockIdx.x * blockDim.x + threadIdx.x;
    if (i < Nn) g_fill[i] = g_rowp[i];
}
__global__ void k_fill_csr(const int* __restrict__ src, const int* __restrict__ dst,
                           const float* __restrict__ w) {
    int e = blockIdx.x * blockDim.x + threadIdx.x;
    if (e < Ee) {
        int s = src[e], t = dst[e];
        int pos = atomicAdd(&g_fill[t], 1);
        g_csrc[pos]  = s;
        g_cnorm[pos] = g_dinv[s] * w[e] * g_dinv[t];
    }
}

// ---------------- split conversion kernels ----------------
__global__ void k_split(const float* __restrict__ in, __nv_bfloat16* __restrict__ out,
                        long total, int K) {
    long idx = (long)blockIdx.x * blockDim.x + threadIdx.x;
    if (idx >= total) return;
    long r = idx / K;
    int  c = (int)(idx - r * K);
    float v = in[idx];
    split_write(v, &out[r * 2 * K + c], &out[r * 2 * K + K + c]);
}
__global__ void k_splitT(const float* __restrict__ in, __nv_bfloat16* __restrict__ out,
                         int Kd, int Md) {
    long idx = (long)blockIdx.x * blockDim.x + threadIdx.x;
    if (idx >= (long)Kd * Md) return;
    int k = (int)(idx / Md);
    int m = (int)(idx - (long)k * Md);
    float v = in[idx];
    split_write(v, &out[(long)m * 2 * Kd + k], &out[(long)m * 2 * Kd + Kd + k]);
}

// ---------------- bf16 mma.sync GEMM, MERGED 3-term split mainloop ----------------
// C[R,M] = A[R,K] @ B[M,K]^T; A/B split: [rows, 2K] = [hi | lo].
// All three products (Ah*Bh + Ah*Bl + Al*Bh) accumulate with weight 1 into the
// SAME acc, so each 32-K chunk loads Ah,Al,Bh,Bl together (4 arrays) and issues
// 48 mma per fragment batch: 33% fewer LDSM, 33% less operand traffic, fewer
// barriers vs the 3-pass variant. Block 128x128, 256 thr, warp 64x32. 2-stage.
// MODE 0: fp32 outF. MODE 1: split bf16 outS. MODE 3: fused fc1|dh1 epilogue.
#define SROW2 40
#define ARR_B (128 * SROW2 * 2)            // bytes per array (Ah/Al/Bh/Bl)
#define STAGE_B (4 * ARR_B)                // 40960
#define GEMM_SMEM (2 * STAGE_B)            // 81920
__global__ void __launch_bounds__(256, 2)
gemm_mma(const __nv_bfloat16* __restrict__ A, const __nv_bfloat16* __restrict__ B,
         const float* __restrict__ bias, float* __restrict__ outF,
         __nv_bfloat16* __restrict__ outS, int R, int M, int K, int ACT, int MODE) {
    extern __shared__ __align__(16) __nv_bfloat16 smg[];
    const uint32_t sbase = (uint32_t)__cvta_generic_to_shared(smg);

    const int tid  = threadIdx.x;
    const int lane = tid & 31, wid = tid >> 5;
    const int wm = wid & 1;
    const int wn = wid >> 1;
    const long rowA = (long)blockIdx.y * 128;
    const long colB = (long)blockIdx.x * 128;
    const int K2 = 2 * K;
    const int NC = K >> 5;                 // 32-K chunks

    float acc[4][4][4];
#pragma unroll
    for (int i = 0; i < 4; i++)
#pragma unroll
        for (int j = 0; j < 4; j++)
#pragma unroll
            for (int k = 0; k < 4; k++) acc[i][j][k] = 0.0f;

    // loader: 4 arrays x 128 rows x 4 segs(16B) = 2048 tasks; 8 per thread
    auto ld_chunk = [&](int c, int buf) {
        int cbase = c * 32;
        uint32_t stg = sbase + (uint32_t)buf * STAGE_B;
#pragma unroll
        for (int u = 0; u < 8; u++) {
            int task = (u << 8) + tid;
            int arr  = task >> 9;          // 0=Ah 1=Al 2=Bh 3=Bl
            int rem  = task & 511;
            int row  = rem >> 2;
            int seg  = rem & 3;
            uint32_t dst = stg + (uint32_t)arr * ARR_B +
                           (uint32_t)(row * SROW2 + seg * 8) * 2;
            int off = ((arr & 1) ? K : 0) + cbase + seg * 8;
            if (arr < 2) {
                long gr = rowA + row;
                cpa16z(dst, A + (gr < R ? gr : 0) * (long)K2 + off, (gr < R) ? 16 : 0);
            } else {
                long gm = colB + row;
                cpa16z(dst, B + (gm < M ? gm : 0) * (long)K2 + off, (gm < M) ? 16 : 0);
            }
        }
        asm volatile("cp.async.commit_group;" ::: "memory");
    };

    ld_chunk(0, 0);

    const uint32_t aOffC = ((uint32_t)(wm * 64 + (lane & 15)) * SROW2 + (lane >> 4) * 8) * 2;
    const uint32_t bOffC = ((uint32_t)(wn * 32 + ((lane >> 4) & 1) * 8 + (lane & 7)) * SROW2 +
                            ((lane >> 3) & 1) * 8) * 2;

    for (int c = 0; c < NC; c++) {
        int buf = c & 1;
        if (c + 1 < NC) {
            ld_chunk(c + 1, buf ^ 1);
            asm volatile("cp.async.wait_group 1;" ::: "memory");
        } else {
            asm volatile("cp.async.wait_group 0;" ::: "memory");
        }
        __syncthreads();
        uint32_t stg = sbase + (uint32_t)buf * STAGE_B;
        uint32_t ah = stg + aOffC;
        uint32_t al = ah + ARR_B;
        uint32_t bh = stg + 2 * ARR_B + bOffC;
        uint32_t bl = bh + ARR_B;
#pragma unroll
        for (int ks = 0; ks < 2; ks++) {
            uint32_t koff = (uint32_t)(ks * 16) * 2;
            uint32_t bhf[2][4], blf[2][4];
#pragma unroll
            for (int nt = 0; nt < 2; nt++) {
                ldsm4(bhf[nt], bh + (uint32_t)(nt * 16 * SROW2) * 2 + koff);
                ldsm4(blf[nt], bl + (uint32_t)(nt * 16 * SROW2) * 2 + koff);
            }
#pragma unroll
            for (int half = 0; half < 2; half++) {
                uint32_t ahf[2][4], alf[2][4];
#pragma unroll
                for (int m2 = 0; m2 < 2; m2++) {
                    int mt = half * 2 + m2;
                    ldsm4(ahf[m2], ah + (uint32_t)(mt * 16 * SROW2) * 2 + koff);
                    ldsm4(alf[m2], al + (uint32_t)(mt * 16 * SROW2) * 2 + koff);
                }
#pragma unroll
                for (int m2 = 0; m2 < 2; m2++) {
                    int mt = half * 2 + m2;
#pragma unroll
                    for (int j = 0; j < 4; j++) {
                        const uint32_t* bhp = &bhf[j >> 1][(j & 1) * 2];
                        const uint32_t* blp = &blf[j >> 1][(j & 1) * 2];
                        mma16816(acc[mt][j], ahf[m2], bhp);
                        mma16816(acc[mt][j], ahf[m2], blp);
                        mma16816(acc[mt][j], alf[m2], bhp);
                    }
                }
            }
        }
        __syncthreads();
    }

    // epilogue
#pragma unroll
    for (int mt = 0; mt < 4; mt++) {
        long r0e = rowA + wm * 64 + mt * 16 + (lane >> 2);
#pragma unroll
        for (int j = 0; j < 4; j++) {
            int col0 = (int)colB + wn * 32 + j * 8 + (lane & 3) * 2;
#pragma unroll
            for (int half = 0; half < 2; half++) {
                long r = r0e + half * 8;
                if (r >= R) continue;
#pragma unroll
                for (int cc = 0; cc < 2; cc++) {
                    int col = col0 + cc;
                    if (col >= M) continue;
                    float v = acc[mt][j][half * 2 + cc];
                    if (bias) v += __ldg(bias + col);
                    if (ACT) v = 0.5f * v * (1.0f + erff(v * 0.7071067811865475f));
                    if (MODE == 0) {
                        outF[r * (long)M + col] = v;
                    } else if (MODE == 1) {
                        split_write(v, &outS[r * (long)(2 * M) + col],
                                       &outS[r * (long)(2 * M) + M + col]);
                    } else {   // MODE 3: fused fc1|dh1
                        if (col < 128)
                            split_write(v, &outS[r * 256 + col], &outS[r * 256 + 128 + col]);
                        else
                            outF[r * 64 + (col - 128)] = v;
                    }
                }
            }
        }
    }
}

// ---------------- batched GCN aggregate + bias + LN + ReLU -> split bf16 ----------------
__global__ void __launch_bounds__(256)
k_gcn_agg_ln_relu(const float* __restrict__ hWAll,
                  const float* __restrict__ bias, const float* __restrict__ g,
                  const float* __restrict__ b, __nv_bfloat16* __restrict__ outAll) {
    const int t = blockIdx.x;
    const int d = threadIdx.x;
    const float* hW = hWAll + (size_t)blockIdx.y * Nn * Dd;
    __nv_bfloat16* out = outAll + (size_t)blockIdx.y * Nn * 512;

    float di = g_dinv[t];
    float acc = di * di * hW[(size_t)t * Dd + d];
    int e0 = g_rowp[t], e1 = g_rowp[t + 1];
#pragma unroll 4
    for (int e = e0; e < e1; e++) {
        int s = __ldg(&g_csrc[e]);
        float nm = __ldg(&g_cnorm[e]);
        acc += nm * __ldg(&hW[(size_t)s * Dd + d]);
    }
    acc += bias[d];

    __shared__ float red[16];
    __shared__ float mv[2];
    float sum = acc, sq = acc * acc;
#pragma unroll
    for (int o = 16; o; o >>= 1) {
        sum += __shfl_down_sync(0xffffffffu, sum, o);
        sq  += __shfl_down_sync(0xffffffffu, sq, o);
    }
    int lane = d & 31, wid = d >> 5;
    if (lane == 0) { red[wid] = sum; red[8 + wid] = sq; }
    __syncthreads();
    if (d == 0) {
        float s = 0.f, q = 0.f;
#pragma unroll
        for (int i = 0; i < 8; i++) { s += red[i]; q += red[8 + i]; }
        float m = s * (1.0f / 256.0f);
        float var = q * (1.0f / 256.0f) - m * m;
        mv[0] = m;
        mv[1] = rsqrtf(var + 1e-5f);
    }
    __syncthreads();
    float val = fmaxf((acc - mv[0]) * mv[1] * g[d] + b[d], 0.0f);
    split_write(val, &out[(size_t)t * 512 + d], &out[(size_t)t * 512 + 256 + d]);
}

// ---------------- GRU cell ----------------
__global__ void k_gru_cell(const float* __restrict__ gi, const float* __restrict__ gh,
                           const float* __restrict__ bhh, const float* __restrict__ hprev,
                           float* __restrict__ hnew, __nv_bfloat16* __restrict__ hs,
                           int first) {
    int idx = blockIdx.x * blockDim.x + threadIdx.x;
    if (idx >= Nn * Dd) return;
    int n = idx >> 8, d = idx & 255;
    const float* gir = gi + (size_t)n * 768;
    float ir = gir[d], iz = gir[256 + d], ig = gir[512 + d];
    float hr, hz, hg, hp;
    if (first) {
        hr = bhh[d]; hz = bhh[256 + d]; hg = bhh[512 + d]; hp = 0.f;
    } else {
        const float* ghr = gh + (size_t)n * 768;
        hr = ghr[d]; hz = ghr[256 + d]; hg = ghr[512 + d];
        hp = hprev[idx];
    }
    float r = 1.0f / (1.0f + expf(-(ir + hr)));
    float z = 1.0f / (1.0f + expf(-(iz + hz)));
    float ng = tanhf(ig + r * hg);
    float v = (1.0f - z) * ng + z * hp;
    hnew[idx] = v;
    split_write(v, &hs[(size_t)n * 512 + d], &hs[(size_t)n * 512 + 256 + d]);
}

// ---------------- tiny head GEMM: out[N,5] = in[N,64] @ W[5,64]^T + b ----------------
__global__ void __launch_bounds__(256)
k_head5(const float* __restrict__ in, const float* __restrict__ W,
        const float* __restrict__ bias, float* __restrict__ out) {
    __shared__ float sW[5 * 64];
    for (int i = threadIdx.x; i < 5 * 64; i += blockDim.x) sW[i] = W[i];
    __syncthreads();
    int gw = (blockIdx.x * blockDim.x + threadIdx.x) >> 5;
    int lane = threadIdx.x & 31;
    if (gw >= Nn) return;
    float x0 = in[(size_t)gw * 64 + lane];
    float x1 = in[(size_t)gw * 64 + 32 + lane];
#pragma unroll
    for (int m = 0; m < 5; m++) {
        float p = x0 * sW[m * 64 + lane] + x1 * sW[m * 64 + 32 + lane];
#pragma unroll
        for (int o = 16; o; o >>= 1) p += __shfl_down_sync(0xffffffffu, p, o);
        if (lane == 0) out[(size_t)gw * 5 + m] = p + bias[m];
    }
}

// ---------------- host orchestration ----------------
template <typename T>
static T* symp(const void* sym) {
    void* p = nullptr;
    cudaGetSymbolAddress(&p, sym);
    return (T*)p;
}

extern "C" void kernel_launch(void* const* d_in, const int* in_sizes, int n_in,
                              void* d_out, int out_size) {
    const float* x    = (const float*)d_in[0];
    const int*   esrc = (const int*)d_in[1];
    const int*   edst = (const int*)d_in[2];
    const float* ew   = (const float*)d_in[3];
    const float* gcnW = (const float*)d_in[4];
    const float* gcnb = (const float*)d_in[5];
    const float* lng  = (const float*)d_in[6];
    const float* lnb  = (const float*)d_in[7];
    const float* Wih  = (const float*)d_in[8];
    const float* Whh  = (const float*)d_in[9];
    const float* bih  = (const float*)d_in[10];
    const float* bhh  = (const float*)d_in[11];
    const float* fc1W = (const float*)d_in[12];
    const float* fc1b = (const float*)d_in[13];
    const float* fc2W = (const float*)d_in[14];
    const float* fc2b = (const float*)d_in[15];
    const float* fc3W = (const float*)d_in[16];
    const float* fc3b = (const float*)d_in[17];
    const float* dh1W = (const float*)d_in[18];
    const float* dh1b = (const float*)d_in[19];
    const float* dh2W = (const float*)d_in[20];
    const float* dh2b = (const float*)d_in[21];

    float* outF = (float*)d_out;
    float* outD = outF + (size_t)Nn * Hh;

    float* tmpW  = symp<float>(g_tmpW);
    float* giAll = symp<float>(g_giAll);
    float* gh    = symp<float>(g_gh);
    float* h1    = symp<float>(g_h1);
    float* h2    = symp<float>(g_h2);
    float* f2    = symp<float>(g_f2);
    float* d1    = symp<float>(g_d1);
    float* cb    = symp<float>(g_cb);
    __nv_bfloat16* xs    = symp<__nv_bfloat16>(g_xs);
    __nv_bfloat16* aggA  = symp<__nv_bfloat16>(g_aggA);
    __nv_bfloat16* seqs  = symp<__nv_bfloat16>(g_seqs);
    __nv_bfloat16* hs    = symp<__nv_bfloat16>(g_hs);
    __nv_bfloat16* f1s   = symp<__nv_bfloat16>(g_f1s);
    __nv_bfloat16* gcnWs = symp<__nv_bfloat16>(g_gcnWs);
    __nv_bfloat16* Wihs  = symp<__nv_bfloat16>(g_Wihs);
    __nv_bfloat16* Whhs  = symp<__nv_bfloat16>(g_Whhs);
    __nv_bfloat16* cWs   = symp<__nv_bfloat16>(g_cWs);
    __nv_bfloat16* fc2Ws = symp<__nv_bfloat16>(g_fc2Ws);

    cudaFuncSetAttribute(gemm_mma, cudaFuncAttributeMaxDynamicSharedMemorySize, GEMM_SMEM);
    cudaFuncSetAttribute(gemm_mma, cudaFuncAttributePreferredSharedMemoryCarveout, 100);

    const int TB = 256;
    const int gN = (Nn + TB - 1) / TB;
    const int gE = (Ee + TB - 1) / TB;

    dim3 blk(256);
    const int RB4 = (SN + 127) / 128;   // 625
    const int RB1 = (Nn + 127) / 128;   // 157
    dim3 gGCN(2, RB4);
    dim3 gGI(6, RB4);
    dim3 gGRU(6, RB1);
    dim3 gHC(2, RB1);
    dim3 gH1(1, RB1);
    dim3 gAgg(Nn, Ss);

    // ---- prologue ordered so the big GCN GEMM stays at launch slot #4 (ncu -s 5) ----
    k_splitT<<<(256 * 256 + TB - 1) / TB, TB>>>(gcnW, gcnWs, 256, 256);                 // #1
    k_split<<<((long)SN * Dd + TB - 1) / TB, TB>>>(x, xs, (long)SN * Dd, 256);          // #2
    k_splitT<<<(256 * 256 + TB - 1) / TB, TB>>>(gcnW + 256 * 256,
                                                gcnWs + 256 * 512, 256, 256);           // #3
    gemm_mma<<<gGCN, blk, GEMM_SMEM>>>(xs, gcnWs, nullptr, tmpW, nullptr,
                                       SN, 256, 256, 0, 0);                             // #4 <- profile
    k_splitT<<<(256 * 256 + TB - 1) / TB, TB>>>(gcnW + 2 * 256 * 256,
                                                gcnWs + 2 * 256 * 512, 256, 256);
    k_split<<<(768 * 256 + TB - 1) / TB, TB>>>(Wih,  Wihs,  (long)768 * 256, 256);
    k_split<<<(768 * 256 + TB - 1) / TB, TB>>>(Whh,  Whhs,  (long)768 * 256, 256);
    k_split<<<(128 * 256 + TB - 1) / TB, TB>>>(fc1W, cWs, (long)128 * 256, 256);
    k_split<<<(64 * 256 + TB - 1) / TB, TB>>>(dh1W, cWs + (size_t)128 * 512, (long)64 * 256, 256);
    k_split<<<(64 * 128 + TB - 1) / TB, TB>>>(fc2W, fc2Ws, (long)64 * 128, 128);
    cudaMemcpyAsync(cb, fc1b, 128 * sizeof(float), cudaMemcpyDeviceToDevice);
    cudaMemcpyAsync(cb + 128, dh1b, 64 * sizeof(float), cudaMemcpyDeviceToDevice);

    // graph preprocessing -> CSR
    k_init_deg_cnt<<<gN, TB>>>();
    k_edge_deg_cnt<<<gE, TB>>>(edst, ew);
    k_dinv<<<gN, TB>>>();
    k_scan<<<1, 1024>>>();
    k_copy_fill<<<gN, TB>>>();
    k_fill_csr<<<gE, TB>>>(esrc, edst, ew);

    // batched GCN stack (layer-0 GEMM already issued above)
    k_gcn_agg_ln_relu<<<gAgg, 256>>>(tmpW, gcnb + 0 * Dd, lng + 0 * Dd, lnb + 0 * Dd, aggA);
    gemm_mma<<<gGCN, blk, GEMM_SMEM>>>(aggA, gcnWs + 1 * 256 * 512, nullptr, tmpW, nullptr,
                                       SN, 256, 256, 0, 0);
    k_gcn_agg_ln_relu<<<gAgg, 256>>>(tmpW, gcnb + 1 * Dd, lng + 1 * Dd, lnb + 1 * Dd, aggA);
    gemm_mma<<<gGCN, blk, GEMM_SMEM>>>(aggA, gcnWs + 2 * 256 * 512, nullptr, tmpW, nullptr,
                                       SN, 256, 256, 0, 0);
    k_gcn_agg_ln_relu<<<gAgg, 256>>>(tmpW, gcnb + 2 * Dd, lng + 2 * Dd, lnb + 2 * Dd, seqs);

    // gi for ALL timesteps in one GEMM
    gemm_mma<<<gGI, blk, GEMM_SMEM>>>(seqs, Wihs, bih, giAll, nullptr, SN, 768, 256, 0, 0);

    // GRU recurrence
    const int gCell = (Nn * Dd + TB - 1) / TB;
    k_gru_cell<<<gCell, TB>>>(giAll, gh, bhh, h1, h1, hs, 1);
    for (int t = 1; t < Ss; t++) {
        float* hp = (t & 1) ? h1 : h2;
        float* hn = (t & 1) ? h2 : h1;
        gemm_mma<<<gGRU, blk, GEMM_SMEM>>>(hs, Whhs, bhh, gh, nullptr, Nn, 768, 256, 0, 0);
        k_gru_cell<<<gCell, TB>>>(giAll + (size_t)t * Nn * 768, gh, bhh, hp, hn, hs, 0);
    }

    // fused fc1|dh1 GEMM (M=192)
    gemm_mma<<<gHC, blk, GEMM_SMEM>>>(hs, cWs, cb, d1, f1s, Nn, 192, 256, 1, 3);
    gemm_mma<<<gH1, blk, GEMM_SMEM>>>(f1s, fc2Ws, fc2b, f2, nullptr, Nn, 64, 128, 1, 0);
    k_head5<<<(Nn * 32 + TB - 1) / TB, TB>>>(f2, fc3W, fc3b, outF);
    k_head5<<<(Nn * 32 + TB - 1) / TB, TB>>>(d1, dh2W, dh2b, outD);
}

// round 11
// speedup vs baseline: 1.9608x; 1.0261x over previous
#include <cuda_runtime.h>
#include <cuda_bf16.h>
#include <math.h>
#include <stdint.h>

#define Nn 20000
#define Dd 256
#define Ss 4
#define Ee 320000
#define Hh 5
#define SN (Ss * Nn)
#define NB 79                      // ceil(Nn/256)

// ---------------- scratch (device globals; no allocs allowed) ----------------
__device__ float g_deg[Nn];
__device__ float g_dinv[Nn];
__device__ int   g_cnt[Nn];
__device__ int   g_rowp[Nn + 1];
__device__ int   g_fill[Nn];
__device__ int   g_bsum[NB + 1];
__device__ int   g_boff[NB + 1];
__device__ int   g_csrc[Ee];
__device__ float g_cnorm[Ee];

__device__ float g_tmpW[SN * Dd];
__device__ float g_giAll[SN * 3 * Dd];
__device__ float g_gh[Nn * 3 * Dd];
__device__ float g_h1[Nn * Dd];
__device__ float g_h2[Nn * Dd];
__device__ float g_f2[Nn * 64];
__device__ float g_d1[Nn * 64];
__device__ float g_cb[192];

// split-bf16 activations: layout [rows, 2K] = [hi | lo]
__device__ __nv_bfloat16 g_xs[SN * 512];
__device__ __nv_bfloat16 g_aggA[SN * 512];
__device__ __nv_bfloat16 g_seqs[SN * 512];
__device__ __nv_bfloat16 g_hs[Nn * 512];
__device__ __nv_bfloat16 g_f1s[Nn * 256];

// split-bf16 weights: [M, 2K]
__device__ __nv_bfloat16 g_gcnWs[3 * 256 * 512];
__device__ __nv_bfloat16 g_Wihs[768 * 512];
__device__ __nv_bfloat16 g_Whhs[768 * 512];
__device__ __nv_bfloat16 g_cWs[192 * 512];
__device__ __nv_bfloat16 g_fc2Ws[64 * 256];

// ---------------- helpers ----------------
__device__ __forceinline__ void split_write(float v, __nv_bfloat16* hi, __nv_bfloat16* lo) {
    __nv_bfloat16 h = __float2bfloat16(v);
    *hi = h;
    *lo = __float2bfloat16(v - __bfloat162float(h));
}
// vectorized split of 4 consecutive values -> two bf162 stores each side
__device__ __forceinline__ void split_write4(float4 v, __nv_bfloat16* hi, __nv_bfloat16* lo) {
    __nv_bfloat16 h0 = __float2bfloat16(v.x), h1 = __float2bfloat16(v.y);
    __nv_bfloat16 h2 = __float2bfloat16(v.z), h3 = __float2bfloat16(v.w);
    __nv_bfloat162 ha; ha.x = h0; ha.y = h1;
    __nv_bfloat162 hb; hb.x = h2; hb.y = h3;
    *reinterpret_cast<__nv_bfloat162*>(hi)     = ha;
    *reinterpret_cast<__nv_bfloat162*>(hi + 2) = hb;
    __nv_bfloat162 la, lb;
    la.x = __float2bfloat16(v.x - __bfloat162float(h0));
    la.y = __float2bfloat16(v.y - __bfloat162float(h1));
    lb.x = __float2bfloat16(v.z - __bfloat162float(h2));
    lb.y = __float2bfloat16(v.w - __bfloat162float(h3));
    *reinterpret_cast<__nv_bfloat162*>(lo)     = la;
    *reinterpret_cast<__nv_bfloat162*>(lo + 2) = lb;
}
__device__ __forceinline__ void ldsm4(uint32_t* r, uint32_t addr) {
    asm volatile("ldmatrix.sync.aligned.m8n8.x4.shared.b16 {%0,%1,%2,%3}, [%4];"
                 : "=r"(r[0]), "=r"(r[1]), "=r"(r[2]), "=r"(r[3]) : "r"(addr));
}
__device__ __forceinline__ void mma16816(float* c, const uint32_t* a, const uint32_t* b) {
    asm volatile(
        "mma.sync.aligned.m16n8k16.row.col.f32.bf16.bf16.f32 "
        "{%0,%1,%2,%3}, {%4,%5,%6,%7}, {%8,%9}, {%0,%1,%2,%3};"
        : "+f"(c[0]), "+f"(c[1]), "+f"(c[2]), "+f"(c[3])
        : "r"(a[0]), "r"(a[1]), "r"(a[2]), "r"(a[3]), "r"(b[0]), "r"(b[1]));
}
__device__ __forceinline__ void cpa16z(uint32_t dst, const void* src, int sz) {
    asm volatile("cp.async.cg.shared.global [%0], [%1], 16, %2;"
                 :: "r"(dst), "l"(src), "r"(sz));
}

// ---------------- graph preprocessing ----------------
__global__ void k_init_deg_cnt() {
    int i = blockIdx.x * blockDim.x + threadIdx.x;
    if (i < Nn) { g_deg[i] = 1.0f; g_cnt[i] = 0; }
}
__global__ void k_edge_deg_cnt(const int* __restrict__ dst, const float* __restrict__ w) {
    int e = blockIdx.x * blockDim.x + threadIdx.x;
    if (e < Ee) {
        int t = dst[e];
        atomicAdd(&g_deg[t], w[e]);
        atomicAdd(&g_cnt[t], 1);
    }
}
__global__ void k_dinv() {
    int i = blockIdx.x * blockDim.x + threadIdx.x;
    if (i < Nn) g_dinv[i] = rsqrtf(g_deg[i]);
}
// scan pass 1: per-block exclusive scan, block totals to g_bsum
__global__ void __launch_bounds__(256) k_scan1() {
    __shared__ int wsum[8];
    int i = blockIdx.x * 256 + threadIdx.x;
    int lane = threadIdx.x & 31, wd = threadIdx.x >> 5;
    int v = (i < Nn) ? g_cnt[i] : 0;
    int x = v;
#pragma unroll
    for (int o = 1; o < 32; o <<= 1) {
        int y = __shfl_up_sync(0xffffffffu, x, o);
        if (lane >= o) x += y;
    }
    if (lane == 31) wsum[wd] = x;
    __syncthreads();
    if (threadIdx.x == 0) {
        int acc = 0;
#pragma unroll
        for (int w = 0; w < 8; w++) { int t = wsum[w]; wsum[w] = acc; acc += t; }
        g_bsum[blockIdx.x] = acc;
    }
    __syncthreads();
    if (i < Nn) g_rowp[i] = wsum[wd] + x - v;
}
// scan pass 2: single warp scans NB block sums
__global__ void k_scan2() {
    int t = threadIdx.x;   // 128 threads
    __shared__ int sh[NB];
    if (t < NB) sh[t] = g_bsum[t];
    __syncthreads();
    if (t == 0) {
        int acc = 0;
        for (int b = 0; b < NB; b++) { int v = sh[b]; g_boff[b] = acc; acc += v; }
        g_rowp[Nn] = acc;
    }
}
// scan pass 3: add block offsets; fused fill-pointer copy
__global__ void __launch_bounds__(256) k_scan3() {
    int i = blockIdx.x * 256 + threadIdx.x;
    if (i < Nn) {
        int r = g_rowp[i] + g_boff[blockIdx.x];
        g_rowp[i] = r;
        g_fill[i] = r;
    }
}
__global__ void k_fill_csr(const int* __restrict__ src, const int* __restrict__ dst,
                           const float* __restrict__ w) {
    int e = blockIdx.x * blockDim.x + threadIdx.x;
    if (e < Ee) {
        int s = src[e], t = dst[e];
        int pos = atomicAdd(&g_fill[t], 1);
        g_csrc[pos]  = s;
        g_cnorm[pos] = g_dinv[s] * w[e] * g_dinv[t];
    }
}

// ---------------- split conversion kernels ----------------
// vectorized: 4 elements per thread along K
__global__ void k_split(const float* __restrict__ in, __nv_bfloat16* __restrict__ out,
                        long total4, int K4) {
    long idx = (long)blockIdx.x * blockDim.x + threadIdx.x;
    if (idx >= total4) return;
    long r = idx / K4;
    int  c = (int)(idx - r * K4) * 4;
    int  K = K4 * 4;
    float4 v = *reinterpret_cast<const float4*>(in + r * K + c);
    split_write4(v, &out[r * 2 * K + c], &out[r * 2 * K + K + c]);
}
__global__ void k_splitT(const float* __restrict__ in, __nv_bfloat16* __restrict__ out,
                         int Kd, int Md) {
    long idx = (long)blockIdx.x * blockDim.x + threadIdx.x;
    if (idx >= (long)Kd * Md) return;
    int k = (int)(idx / Md);
    int m = (int)(idx - (long)k * Md);
    float v = in[idx];
    split_write(v, &out[(long)m * 2 * Kd + k], &out[(long)m * 2 * Kd + Kd + k]);
}

// ---------------- bf16 mma.sync GEMM, merged split, RAW-chain-free term sweeps ----
// C[R,M] = A[R,K] @ B[M,K]^T; A/B split: [rows, 2K] = [hi | lo].
// Per k-step the three term sweeps (hh, hl, lh) each touch 8 INDEPENDENT
// accumulators before any acc is revisited -> no mma RAW stalls.
#define SROW2 40
#define ARR_B (128 * SROW2 * 2)
#define STAGE_B (4 * ARR_B)
#define GEMM_SMEM (2 * STAGE_B)
__global__ void __launch_bounds__(256, 2)
gemm_mma(const __nv_bfloat16* __restrict__ A, const __nv_bfloat16* __restrict__ B,
         const float* __restrict__ bias, float* __restrict__ outF,
         __nv_bfloat16* __restrict__ outS, int R, int M, int K, int ACT, int MODE) {
    extern __shared__ __align__(16) __nv_bfloat16 smg[];
    const uint32_t sbase = (uint32_t)__cvta_generic_to_shared(smg);

    const int tid  = threadIdx.x;
    const int lane = tid & 31, wid = tid >> 5;
    const int wm = wid & 1;
    const int wn = wid >> 1;
    const long rowA = (long)blockIdx.y * 128;
    const long colB = (long)blockIdx.x * 128;
    const int K2 = 2 * K;
    const int NC = K >> 5;

    float acc[4][4][4];
#pragma unroll
    for (int i = 0; i < 4; i++)
#pragma unroll
        for (int j = 0; j < 4; j++)
#pragma unroll
            for (int k = 0; k < 4; k++) acc[i][j][k] = 0.0f;

    auto ld_chunk = [&](int c, int buf) {
        int cbase = c * 32;
        uint32_t stg = sbase + (uint32_t)buf * STAGE_B;
#pragma unroll
        for (int u = 0; u < 8; u++) {
            int task = (u << 8) + tid;
            int arr  = task >> 9;
            int rem  = task & 511;
            int row  = rem >> 2;
            int seg  = rem & 3;
            uint32_t dst = stg + (uint32_t)arr * ARR_B +
                           (uint32_t)(row * SROW2 + seg * 8) * 2;
            int off = ((arr & 1) ? K : 0) + cbase + seg * 8;
            if (arr < 2) {
                long gr = rowA + row;
                cpa16z(dst, A + (gr < R ? gr : 0) * (long)K2 + off, (gr < R) ? 16 : 0);
            } else {
                long gm = colB + row;
                cpa16z(dst, B + (gm < M ? gm : 0) * (long)K2 + off, (gm < M) ? 16 : 0);
            }
        }
        asm volatile("cp.async.commit_group;" ::: "memory");
    };

    ld_chunk(0, 0);

    const uint32_t aOffC = ((uint32_t)(wm * 64 + (lane & 15)) * SROW2 + (lane >> 4) * 8) * 2;
    const uint32_t bOffC = ((uint32_t)(wn * 32 + ((lane >> 4) & 1) * 8 + (lane & 7)) * SROW2 +
                            ((lane >> 3) & 1) * 8) * 2;

    for (int c = 0; c < NC; c++) {
        int buf = c & 1;
        if (c + 1 < NC) {
            ld_chunk(c + 1, buf ^ 1);
            asm volatile("cp.async.wait_group 1;" ::: "memory");
        } else {
            asm volatile("cp.async.wait_group 0;" ::: "memory");
        }
        __syncthreads();
        uint32_t stg = sbase + (uint32_t)buf * STAGE_B;
        uint32_t ah = stg + aOffC;
        uint32_t al = ah + ARR_B;
        uint32_t bh = stg + 2 * ARR_B + bOffC;
        uint32_t bl = bh + ARR_B;
#pragma unroll
        for (int ks = 0; ks < 2; ks++) {
            uint32_t koff = (uint32_t)(ks * 16) * 2;
            uint32_t bhf[2][4], blf[2][4];
#pragma unroll
            for (int nt = 0; nt < 2; nt++) {
                ldsm4(bhf[nt], bh + (uint32_t)(nt * 16 * SROW2) * 2 + koff);
                ldsm4(blf[nt], bl + (uint32_t)(nt * 16 * SROW2) * 2 + koff);
            }
#pragma unroll
            for (int half = 0; half < 2; half++) {
                uint32_t ahf[2][4], alf[2][4];
#pragma unroll
                for (int m2 = 0; m2 < 2; m2++) {
                    int mt = half * 2 + m2;
                    ldsm4(ahf[m2], ah + (uint32_t)(mt * 16 * SROW2) * 2 + koff);
                    ldsm4(alf[m2], al + (uint32_t)(mt * 16 * SROW2) * 2 + koff);
                }
                // term sweep 0: Ah*Bh over 8 independent accumulators
#pragma unroll
                for (int m2 = 0; m2 < 2; m2++)
#pragma unroll
                    for (int j = 0; j < 4; j++)
                        mma16816(acc[half * 2 + m2][j], ahf[m2], &bhf[j >> 1][(j & 1) * 2]);
                // term sweep 1: Ah*Bl
#pragma unroll
                for (int m2 = 0; m2 < 2; m2++)
#pragma unroll
                    for (int j = 0; j < 4; j++)
                        mma16816(acc[half * 2 + m2][j], ahf[m2], &blf[j >> 1][(j & 1) * 2]);
                // term sweep 2: Al*Bh
#pragma unroll
                for (int m2 = 0; m2 < 2; m2++)
#pragma unroll
                    for (int j = 0; j < 4; j++)
                        mma16816(acc[half * 2 + m2][j], alf[m2], &bhf[j >> 1][(j & 1) * 2]);
            }
        }
        __syncthreads();
    }

    // epilogue
#pragma unroll
    for (int mt = 0; mt < 4; mt++) {
        long r0e = rowA + wm * 64 + mt * 16 + (lane >> 2);
#pragma unroll
        for (int j = 0; j < 4; j++) {
            int col0 = (int)colB + wn * 32 + j * 8 + (lane & 3) * 2;
#pragma unroll
            for (int half = 0; half < 2; half++) {
                long r = r0e + half * 8;
                if (r >= R) continue;
#pragma unroll
                for (int cc = 0; cc < 2; cc++) {
                    int col = col0 + cc;
                    if (col >= M) continue;
                    float v = acc[mt][j][half * 2 + cc];
                    if (bias) v += __ldg(bias + col);
                    if (ACT) v = 0.5f * v * (1.0f + erff(v * 0.7071067811865475f));
                    if (MODE == 0) {
                        outF[r * (long)M + col] = v;
                    } else if (MODE == 1) {
                        split_write(v, &outS[r * (long)(2 * M) + col],
                                       &outS[r * (long)(2 * M) + M + col]);
                    } else {
                        if (col < 128)
                            split_write(v, &outS[r * 256 + col], &outS[r * 256 + 128 + col]);
                        else
                            outF[r * 64 + (col - 128)] = v;
                    }
                }
            }
        }
    }
}

// ---------------- batched GCN aggregate + bias + LN + ReLU -> split bf16 ----------------
__global__ void __launch_bounds__(256)
k_gcn_agg_ln_relu(const float* __restrict__ hWAll,
                  const float* __restrict__ bias, const float* __restrict__ g,
                  const float* __restrict__ b, __nv_bfloat16* __restrict__ outAll) {
    const int t = blockIdx.x;
    const int d = threadIdx.x;
    const float* hW = hWAll + (size_t)blockIdx.y * Nn * Dd;
    __nv_bfloat16* out = outAll + (size_t)blockIdx.y * Nn * 512;

    float di = g_dinv[t];
    float acc = di * di * hW[(size_t)t * Dd + d];
    int e0 = g_rowp[t], e1 = g_rowp[t + 1];
#pragma unroll 4
    for (int e = e0; e < e1; e++) {
        int s = __ldg(&g_csrc[e]);
        float nm = __ldg(&g_cnorm[e]);
        acc += nm * __ldg(&hW[(size_t)s * Dd + d]);
    }
    acc += bias[d];

    __shared__ float red[16];
    __shared__ float mv[2];
    float sum = acc, sq = acc * acc;
#pragma unroll
    for (int o = 16; o; o >>= 1) {
        sum += __shfl_down_sync(0xffffffffu, sum, o);
        sq  += __shfl_down_sync(0xffffffffu, sq, o);
    }
    int lane = d & 31, wid = d >> 5;
    if (lane == 0) { red[wid] = sum; red[8 + wid] = sq; }
    __syncthreads();
    if (d == 0) {
        float s = 0.f, q = 0.f;
#pragma unroll
        for (int i = 0; i < 8; i++) { s += red[i]; q += red[8 + i]; }
        float m = s * (1.0f / 256.0f);
        float var = q * (1.0f / 256.0f) - m * m;
        mv[0] = m;
        mv[1] = rsqrtf(var + 1e-5f);
    }
    __syncthreads();
    float val = fmaxf((acc - mv[0]) * mv[1] * g[d] + b[d], 0.0f);
    split_write(val, &out[(size_t)t * 512 + d], &out[(size_t)t * 512 + 256 + d]);
}

// ---------------- GRU cell, float4 vectorized ----------------
__global__ void k_gru_cell(const float* __restrict__ gi, const float* __restrict__ gh,
                           const float* __restrict__ bhh, const float* __restrict__ hprev,
                           float* __restrict__ hnew, __nv_bfloat16* __restrict__ hs,
                           int first) {
    int idx = blockIdx.x * blockDim.x + threadIdx.x;   // over Nn*64 float4 groups
    if (idx >= Nn * 64) return;
    int n = idx >> 6, d = (idx & 63) << 2;
    const float* gir = gi + (size_t)n * 768;
    float4 ir = *reinterpret_cast<const float4*>(gir + d);
    float4 iz = *reinterpret_cast<const float4*>(gir + 256 + d);
    float4 ig = *reinterpret_cast<const float4*>(gir + 512 + d);
    float4 hr, hz, hg, hp;
    if (first) {
        hr = *reinterpret_cast<const float4*>(bhh + d);
        hz = *reinterpret_cast<const float4*>(bhh + 256 + d);
        hg = *reinterpret_cast<const float4*>(bhh + 512 + d);
        hp = make_float4(0.f, 0.f, 0.f, 0.f);
    } else {
        const float* ghr = gh + (size_t)n * 768;
        hr = *reinterpret_cast<const float4*>(ghr + d);
        hz = *reinterpret_cast<const float4*>(ghr + 256 + d);
        hg = *reinterpret_cast<const float4*>(ghr + 512 + d);
        hp = *reinterpret_cast<const float4*>(hprev + (size_t)n * 256 + d);
    }
    float4 v;
#define GRU1(c) { \
        float r = 1.0f / (1.0f + expf(-(ir.c + hr.c))); \
        float z = 1.0f / (1.0f + expf(-(iz.c + hz.c))); \
        float ng = tanhf(ig.c + r * hg.c); \
        v.c = (1.0f - z) * ng + z * hp.c; }
    GRU1(x) GRU1(y) GRU1(z) GRU1(w)
#undef GRU1
    *reinterpret_cast<float4*>(hnew + (size_t)n * 256 + d) = v;
    split_write4(v, &hs[(size_t)n * 512 + d], &hs[(size_t)n * 512 + 256 + d]);
}

// ---------------- tiny head GEMM ----------------
__global__ void __launch_bounds__(256)
k_head5(const float* __restrict__ in, const float* __restrict__ W,
        const float* __restrict__ bias, float* __restrict__ out) {
    __shared__ float sW[5 * 64];
    for (int i = threadIdx.x; i < 5 * 64; i += blockDim.x) sW[i] = W[i];
    __syncthreads();
    int gw = (blockIdx.x * blockDim.x + threadIdx.x) >> 5;
    int lane = threadIdx.x & 31;
    if (gw >= Nn) return;
    float x0 = in[(size_t)gw * 64 + lane];
    float x1 = in[(size_t)gw * 64 + 32 + lane];
#pragma unroll
    for (int m = 0; m < 5; m++) {
        float p = x0 * sW[m * 64 + lane] + x1 * sW[m * 64 + 32 + lane];
#pragma unroll
        for (int o = 16; o; o >>= 1) p += __shfl_down_sync(0xffffffffu, p, o);
        if (lane == 0) out[(size_t)gw * 5 + m] = p + bias[m];
    }
}

// ---------------- host orchestration ----------------
template <typename T>
static T* symp(const void* sym) {
    void* p = nullptr;
    cudaGetSymbolAddress(&p, sym);
    return (T*)p;
}

extern "C" void kernel_launch(void* const* d_in, const int* in_sizes, int n_in,
                              void* d_out, int out_size) {
    const float* x    = (const float*)d_in[0];
    const int*   esrc = (const int*)d_in[1];
    const int*   edst = (const int*)d_in[2];
    const float* ew   = (const float*)d_in[3];
    const float* gcnW = (const float*)d_in[4];
    const float* gcnb = (const float*)d_in[5];
    const float* lng  = (const float*)d_in[6];
    const float* lnb  = (const float*)d_in[7];
    const float* Wih  = (const float*)d_in[8];
    const float* Whh  = (const float*)d_in[9];
    const float* bih  = (const float*)d_in[10];
    const float* bhh  = (const float*)d_in[11];
    const float* fc1W = (const float*)d_in[12];
    const float* fc1b = (const float*)d_in[13];
    const float* fc2W = (const float*)d_in[14];
    const float* fc2b = (const float*)d_in[15];
    const float* fc3W = (const float*)d_in[16];
    const float* fc3b = (const float*)d_in[17];
    const float* dh1W = (const float*)d_in[18];
    const float* dh1b = (const float*)d_in[19];
    const float* dh2W = (const float*)d_in[20];
    const float* dh2b = (const float*)d_in[21];

    float* outF = (float*)d_out;
    float* outD = outF + (size_t)Nn * Hh;

    float* tmpW  = symp<float>(g_tmpW);
    float* giAll = symp<float>(g_giAll);
    float* gh    = symp<float>(g_gh);
    float* h1    = symp<float>(g_h1);
    float* h2    = symp<float>(g_h2);
    float* f2    = symp<float>(g_f2);
    float* d1    = symp<float>(g_d1);
    float* cb    = symp<float>(g_cb);
    __nv_bfloat16* xs    = symp<__nv_bfloat16>(g_xs);
    __nv_bfloat16* aggA  = symp<__nv_bfloat16>(g_aggA);
    __nv_bfloat16* seqs  = symp<__nv_bfloat16>(g_seqs);
    __nv_bfloat16* hs    = symp<__nv_bfloat16>(g_hs);
    __nv_bfloat16* f1s   = symp<__nv_bfloat16>(g_f1s);
    __nv_bfloat16* gcnWs = symp<__nv_bfloat16>(g_gcnWs);
    __nv_bfloat16* Wihs  = symp<__nv_bfloat16>(g_Wihs);
    __nv_bfloat16* Whhs  = symp<__nv_bfloat16>(g_Whhs);
    __nv_bfloat16* cWs   = symp<__nv_bfloat16>(g_cWs);
    __nv_bfloat16* fc2Ws = symp<__nv_bfloat16>(g_fc2Ws);

    cudaFuncSetAttribute(gemm_mma, cudaFuncAttributeMaxDynamicSharedMemorySize, GEMM_SMEM);
    cudaFuncSetAttribute(gemm_mma, cudaFuncAttributePreferredSharedMemoryCarveout, 100);

    const int TB = 256;
    const int gN = (Nn + TB - 1) / TB;
    const int gE = (Ee + TB - 1) / TB;

    dim3 blk(256);
    const int RB4 = (SN + 127) / 128;   // 625
    const int RB1 = (Nn + 127) / 128;   // 157
    dim3 gGCN(2, RB4);
    dim3 gGI(6, RB4);
    dim3 gGRU(6, RB1);
    dim3 gHC(2, RB1);
    dim3 gH1(1, RB1);
    dim3 gAgg(Nn, Ss);

    // ---- prologue ordered so the big GCN GEMM stays at launch slot #4 (ncu -s 5) ----
    k_splitT<<<(256 * 256 + TB - 1) / TB, TB>>>(gcnW, gcnWs, 256, 256);                 // #1
    k_split<<<((long)SN * 64 + TB - 1) / TB, TB>>>(x, xs, (long)SN * 64, 64);           // #2
    k_splitT<<<(256 * 256 + TB - 1) / TB, TB>>>(gcnW + 256 * 256,
                                                gcnWs + 256 * 512, 256, 256);           // #3
    gemm_mma<<<gGCN, blk, GEMM_SMEM>>>(xs, gcnWs, nullptr, tmpW, nullptr,
                                       SN, 256, 256, 0, 0);                             // #4 <- profile
    k_splitT<<<(256 * 256 + TB - 1) / TB, TB>>>(gcnW + 2 * 256 * 256,
                                                gcnWs + 2 * 256 * 512, 256, 256);
    k_split<<<(768 * 64 + TB - 1) / TB, TB>>>(Wih,  Wihs,  (long)768 * 64, 64);
    k_split<<<(768 * 64 + TB - 1) / TB, TB>>>(Whh,  Whhs,  (long)768 * 64, 64);
    k_split<<<(128 * 64 + TB - 1) / TB, TB>>>(fc1W, cWs, (long)128 * 64, 64);
    k_split<<<(64 * 64 + TB - 1) / TB, TB>>>(dh1W, cWs + (size_t)128 * 512, (long)64 * 64, 64);
    k_split<<<(64 * 32 + TB - 1) / TB, TB>>>(fc2W, fc2Ws, (long)64 * 32, 32);
    cudaMemcpyAsync(cb, fc1b, 128 * sizeof(float), cudaMemcpyDeviceToDevice);
    cudaMemcpyAsync(cb + 128, dh1b, 64 * sizeof(float), cudaMemcpyDeviceToDevice);

    // graph preprocessing -> CSR (fast 3-pass scan; fill-copy fused into pass 3)
    k_init_deg_cnt<<<gN, TB>>>();
    k_edge_deg_cnt<<<gE, TB>>>(edst, ew);
    k_dinv<<<gN, TB>>>();
    k_scan1<<<NB, 256>>>();
    k_scan2<<<1, 128>>>();
    k_scan3<<<NB, 256>>>();
    k_fill_csr<<<gE, TB>>>(esrc, edst, ew);

    // batched GCN stack (layer-0 GEMM already issued above)
    k_gcn_agg_ln_relu<<<gAgg, 256>>>(tmpW, gcnb + 0 * Dd, lng + 0 * Dd, lnb + 0 * Dd, aggA);
    gemm_mma<<<gGCN, blk, GEMM_SMEM>>>(aggA, gcnWs + 1 * 256 * 512, nullptr, tmpW, nullptr,
                                       SN, 256, 256, 0, 0);
    k_gcn_agg_ln_relu<<<gAgg, 256>>>(tmpW, gcnb + 1 * Dd, lng + 1 * Dd, lnb + 1 * Dd, aggA);
    gemm_mma<<<gGCN, blk, GEMM_SMEM>>>(aggA, gcnWs + 2 * 256 * 512, nullptr, tmpW, nullptr,
                                       SN, 256, 256, 0, 0);
    k_gcn_agg_ln_relu<<<gAgg, 256>>>(tmpW, gcnb + 2 * Dd, lng + 2 * Dd, lnb + 2 * Dd, seqs);

    // gi for ALL timesteps in one GEMM
    gemm_mma<<<gGI, blk, GEMM_SMEM>>>(seqs, Wihs, bih, giAll, nullptr, SN, 768, 256, 0, 0);

    // GRU recurrence
    const int gCell = (Nn * 64 + TB - 1) / TB;
    k_gru_cell<<<gCell, TB>>>(giAll, gh, bhh, h1, h1, hs, 1);
    for (int t = 1; t < Ss; t++) {
        float* hp = (t & 1) ? h1 : h2;
        float* hn = (t & 1) ? h2 : h1;
        gemm_mma<<<gGRU, blk, GEMM_SMEM>>>(hs, Whhs, bhh, gh, nullptr, Nn, 768, 256, 0, 0);
        k_gru_cell<<<gCell, TB>>>(giAll + (size_t)t * Nn * 768, gh, bhh, hp, hn, hs, 0);
    }

    // fused fc1|dh1 GEMM (M=192)
    gemm_mma<<<gHC, blk, GEMM_SMEM>>>(hs, cWs, cb, d1, f1s, Nn, 192, 256, 1, 3);
    gemm_mma<<<gH1, blk, GEMM_SMEM>>>(f1s, fc2Ws, fc2b, f2, nullptr, Nn, 64, 128, 1, 0);
    k_head5<<<(Nn * 32 + TB - 1) / TB, TB>>>(f2, fc3W, fc3b, outF);
    k_head5<<<(Nn * 32 + TB - 1) / TB, TB>>>(d1, dh2W, dh2b, outD);
}

// round 12
// speedup vs baseline: 2.3074x; 1.1768x over previous
#include <cuda_runtime.h>
#include <cuda_bf16.h>
#include <math.h>
#include <stdint.h>

#define Nn 20000
#define Dd 256
#define Ss 4
#define Ee 320000
#define Hh 5
#define SN (Ss * Nn)
#define NB 79                      // ceil(Nn/256)

// ---------------- scratch (device globals; no allocs allowed) ----------------
__device__ float g_deg[Nn];
__device__ float g_dinv[Nn];
__device__ int   g_cnt[Nn];
__device__ int   g_rowp[Nn + 1];
__device__ int   g_fill[Nn];
__device__ int   g_bsum[NB + 1];
__device__ int   g_boff[NB + 1];
__device__ int   g_csrc[Ee];
__device__ float g_cnorm[Ee];

__device__ float g_tmpW[SN * Dd];
__device__ float g_giAll[SN * 3 * Dd];
__device__ float g_gh[Nn * 3 * Dd];
__device__ float g_h1[Nn * Dd];
__device__ float g_h2[Nn * Dd];
__device__ float g_f2[Nn * 64];
__device__ float g_d1[Nn * 64];
__device__ float g_cb[192];

// split-bf16 activations: layout [rows, 2K] = [hi | lo]
__device__ __nv_bfloat16 g_xs[SN * 512];
__device__ __nv_bfloat16 g_aggA[SN * 512];
__device__ __nv_bfloat16 g_seqs[SN * 512];
__device__ __nv_bfloat16 g_hs[Nn * 512];
__device__ __nv_bfloat16 g_f1s[Nn * 256];

// split-bf16 weights: [M, 2K]
__device__ __nv_bfloat16 g_gcnWs[3 * 256 * 512];
__device__ __nv_bfloat16 g_Wihs[768 * 512];
__device__ __nv_bfloat16 g_Whhs[768 * 512];
__device__ __nv_bfloat16 g_cWs[192 * 512];
__device__ __nv_bfloat16 g_fc2Ws[64 * 256];

// ---------------- helpers ----------------
__device__ __forceinline__ void split_write(float v, __nv_bfloat16* hi, __nv_bfloat16* lo) {
    __nv_bfloat16 h = __float2bfloat16(v);
    *hi = h;
    *lo = __float2bfloat16(v - __bfloat162float(h));
}
__device__ __forceinline__ void split_write4(float4 v, __nv_bfloat16* hi, __nv_bfloat16* lo) {
    __nv_bfloat16 h0 = __float2bfloat16(v.x), h1 = __float2bfloat16(v.y);
    __nv_bfloat16 h2 = __float2bfloat16(v.z), h3 = __float2bfloat16(v.w);
    __nv_bfloat162 ha; ha.x = h0; ha.y = h1;
    __nv_bfloat162 hb; hb.x = h2; hb.y = h3;
    *reinterpret_cast<__nv_bfloat162*>(hi)     = ha;
    *reinterpret_cast<__nv_bfloat162*>(hi + 2) = hb;
    __nv_bfloat162 la, lb;
    la.x = __float2bfloat16(v.x - __bfloat162float(h0));
    la.y = __float2bfloat16(v.y - __bfloat162float(h1));
    lb.x = __float2bfloat16(v.z - __bfloat162float(h2));
    lb.y = __float2bfloat16(v.w - __bfloat162float(h3));
    *reinterpret_cast<__nv_bfloat162*>(lo)     = la;
    *reinterpret_cast<__nv_bfloat162*>(lo + 2) = lb;
}
__device__ __forceinline__ void ldsm4(uint32_t* r, uint32_t addr) {
    asm volatile("ldmatrix.sync.aligned.m8n8.x4.shared.b16 {%0,%1,%2,%3}, [%4];"
                 : "=r"(r[0]), "=r"(r[1]), "=r"(r[2]), "=r"(r[3]) : "r"(addr));
}
__device__ __forceinline__ void mma16816(float* c, const uint32_t* a, const uint32_t* b) {
    asm volatile(
        "mma.sync.aligned.m16n8k16.row.col.f32.bf16.bf16.f32 "
        "{%0,%1,%2,%3}, {%4,%5,%6,%7}, {%8,%9}, {%0,%1,%2,%3};"
        : "+f"(c[0]), "+f"(c[1]), "+f"(c[2]), "+f"(c[3])
        : "r"(a[0]), "r"(a[1]), "r"(a[2]), "r"(a[3]), "r"(b[0]), "r"(b[1]));
}
__device__ __forceinline__ void cpa16z(uint32_t dst, const void* src, int sz) {
    asm volatile("cp.async.cg.shared.global [%0], [%1], 16, %2;"
                 :: "r"(dst), "l"(src), "r"(sz));
}

// ---------------- graph preprocessing ----------------
__global__ void k_init_deg_cnt() {
    int i = blockIdx.x * blockDim.x + threadIdx.x;
    if (i < Nn) { g_deg[i] = 1.0f; g_cnt[i] = 0; }
}
__global__ void k_edge_deg_cnt(const int* __restrict__ dst, const float* __restrict__ w) {
    int e = blockIdx.x * blockDim.x + threadIdx.x;
    if (e < Ee) {
        int t = dst[e];
        atomicAdd(&g_deg[t], w[e]);
        atomicAdd(&g_cnt[t], 1);
    }
}
__global__ void k_dinv() {
    int i = blockIdx.x * blockDim.x + threadIdx.x;
    if (i < Nn) g_dinv[i] = rsqrtf(g_deg[i]);
}
__global__ void __launch_bounds__(256) k_scan1() {
    __shared__ int wsum[8];
    int i = blockIdx.x * 256 + threadIdx.x;
    int lane = threadIdx.x & 31, wd = threadIdx.x >> 5;
    int v = (i < Nn) ? g_cnt[i] : 0;
    int x = v;
#pragma unroll
    for (int o = 1; o < 32; o <<= 1) {
        int y = __shfl_up_sync(0xffffffffu, x, o);
        if (lane >= o) x += y;
    }
    if (lane == 31) wsum[wd] = x;
    __syncthreads();
    if (threadIdx.x == 0) {
        int acc = 0;
#pragma unroll
        for (int w = 0; w < 8; w++) { int t = wsum[w]; wsum[w] = acc; acc += t; }
        g_bsum[blockIdx.x] = acc;
    }
    __syncthreads();
    if (i < Nn) g_rowp[i] = wsum[wd] + x - v;
}
__global__ void k_scan2() {
    int t = threadIdx.x;
    __shared__ int sh[NB];
    if (t < NB) sh[t] = g_bsum[t];
    __syncthreads();
    if (t == 0) {
        int acc = 0;
        for (int b = 0; b < NB; b++) { int v = sh[b]; g_boff[b] = acc; acc += v; }
        g_rowp[Nn] = acc;
    }
}
__global__ void __launch_bounds__(256) k_scan3() {
    int i = blockIdx.x * 256 + threadIdx.x;
    if (i < Nn) {
        int r = g_rowp[i] + g_boff[blockIdx.x];
        g_rowp[i] = r;
        g_fill[i] = r;
    }
}
__global__ void k_fill_csr(const int* __restrict__ src, const int* __restrict__ dst,
                           const float* __restrict__ w) {
    int e = blockIdx.x * blockDim.x + threadIdx.x;
    if (e < Ee) {
        int s = src[e], t = dst[e];
        int pos = atomicAdd(&g_fill[t], 1);
        g_csrc[pos]  = s;
        g_cnorm[pos] = g_dinv[s] * w[e] * g_dinv[t];
    }
}

// ---------------- split conversion kernels ----------------
__global__ void k_split(const float* __restrict__ in, __nv_bfloat16* __restrict__ out,
                        long total4, int K4) {
    long idx = (long)blockIdx.x * blockDim.x + threadIdx.x;
    if (idx >= total4) return;
    long r = idx / K4;
    int  c = (int)(idx - r * K4) * 4;
    int  K = K4 * 4;
    float4 v = *reinterpret_cast<const float4*>(in + r * K + c);
    split_write4(v, &out[r * 2 * K + c], &out[r * 2 * K + K + c]);
}
__global__ void k_splitT(const float* __restrict__ in, __nv_bfloat16* __restrict__ out,
                         int Kd, int Md) {
    long idx = (long)blockIdx.x * blockDim.x + threadIdx.x;
    if (idx >= (long)Kd * Md) return;
    int k = (int)(idx / Md);
    int m = (int)(idx - (long)k * Md);
    float v = in[idx];
    split_write(v, &out[(long)m * 2 * Kd + k], &out[(long)m * 2 * Kd + Kd + k]);
}

// ---------------- bf16 mma.sync GEMM (R11 core, unchanged) ----------------
#define SROW2 40
#define ARR_B (128 * SROW2 * 2)
#define STAGE_B (4 * ARR_B)
#define GEMM_SMEM (2 * STAGE_B)
__global__ void __launch_bounds__(256, 2)
gemm_mma(const __nv_bfloat16* __restrict__ A, const __nv_bfloat16* __restrict__ B,
         const float* __restrict__ bias, float* __restrict__ outF,
         __nv_bfloat16* __restrict__ outS, int R, int M, int K, int ACT, int MODE) {
    extern __shared__ __align__(16) __nv_bfloat16 smg[];
    const uint32_t sbase = (uint32_t)__cvta_generic_to_shared(smg);

    const int tid  = threadIdx.x;
    const int lane = tid & 31, wid = tid >> 5;
    const int wm = wid & 1;
    const int wn = wid >> 1;
    const long rowA = (long)blockIdx.y * 128;
    const long colB = (long)blockIdx.x * 128;
    const int K2 = 2 * K;
    const int NC = K >> 5;

    float acc[4][4][4];
#pragma unroll
    for (int i = 0; i < 4; i++)
#pragma unroll
        for (int j = 0; j < 4; j++)
#pragma unroll
            for (int k = 0; k < 4; k++) acc[i][j][k] = 0.0f;

    auto ld_chunk = [&](int c, int buf) {
        int cbase = c * 32;
        uint32_t stg = sbase + (uint32_t)buf * STAGE_B;
#pragma unroll
        for (int u = 0; u < 8; u++) {
            int task = (u << 8) + tid;
            int arr  = task >> 9;
            int rem  = task & 511;
            int row  = rem >> 2;
            int seg  = rem & 3;
            uint32_t dst = stg + (uint32_t)arr * ARR_B +
                           (uint32_t)(row * SROW2 + seg * 8) * 2;
            int off = ((arr & 1) ? K : 0) + cbase + seg * 8;
            if (arr < 2) {
                long gr = rowA + row;
                cpa16z(dst, A + (gr < R ? gr : 0) * (long)K2 + off, (gr < R) ? 16 : 0);
            } else {
                long gm = colB + row;
                cpa16z(dst, B + (gm < M ? gm : 0) * (long)K2 + off, (gm < M) ? 16 : 0);
            }
        }
        asm volatile("cp.async.commit_group;" ::: "memory");
    };

    ld_chunk(0, 0);

    const uint32_t aOffC = ((uint32_t)(wm * 64 + (lane & 15)) * SROW2 + (lane >> 4) * 8) * 2;
    const uint32_t bOffC = ((uint32_t)(wn * 32 + ((lane >> 4) & 1) * 8 + (lane & 7)) * SROW2 +
                            ((lane >> 3) & 1) * 8) * 2;

    for (int c = 0; c < NC; c++) {
        int buf = c & 1;
        if (c + 1 < NC) {
            ld_chunk(c + 1, buf ^ 1);
            asm volatile("cp.async.wait_group 1;" ::: "memory");
        } else {
            asm volatile("cp.async.wait_group 0;" ::: "memory");
        }
        __syncthreads();
        uint32_t stg = sbase + (uint32_t)buf * STAGE_B;
        uint32_t ah = stg + aOffC;
        uint32_t al = ah + ARR_B;
        uint32_t bh = stg + 2 * ARR_B + bOffC;
        uint32_t bl = bh + ARR_B;
#pragma unroll
        for (int ks = 0; ks < 2; ks++) {
            uint32_t koff = (uint32_t)(ks * 16) * 2;
            uint32_t bhf[2][4], blf[2][4];
#pragma unroll
            for (int nt = 0; nt < 2; nt++) {
                ldsm4(bhf[nt], bh + (uint32_t)(nt * 16 * SROW2) * 2 + koff);
                ldsm4(blf[nt], bl + (uint32_t)(nt * 16 * SROW2) * 2 + koff);
            }
#pragma unroll
            for (int half = 0; half < 2; half++) {
                uint32_t ahf[2][4], alf[2][4];
#pragma unroll
                for (int m2 = 0; m2 < 2; m2++) {
                    int mt = half * 2 + m2;
                    ldsm4(ahf[m2], ah + (uint32_t)(mt * 16 * SROW2) * 2 + koff);
                    ldsm4(alf[m2], al + (uint32_t)(mt * 16 * SROW2) * 2 + koff);
                }
#pragma unroll
                for (int m2 = 0; m2 < 2; m2++)
#pragma unroll
                    for (int j = 0; j < 4; j++)
                        mma16816(acc[half * 2 + m2][j], ahf[m2], &bhf[j >> 1][(j & 1) * 2]);
#pragma unroll
                for (int m2 = 0; m2 < 2; m2++)
#pragma unroll
                    for (int j = 0; j < 4; j++)
                        mma16816(acc[half * 2 + m2][j], ahf[m2], &blf[j >> 1][(j & 1) * 2]);
#pragma unroll
                for (int m2 = 0; m2 < 2; m2++)
#pragma unroll
                    for (int j = 0; j < 4; j++)
                        mma16816(acc[half * 2 + m2][j], alf[m2], &bhf[j >> 1][(j & 1) * 2]);
            }
        }
        __syncthreads();
    }

    // epilogue
#pragma unroll
    for (int mt = 0; mt < 4; mt++) {
        long r0e = rowA + wm * 64 + mt * 16 + (lane >> 2);
#pragma unroll
        for (int j = 0; j < 4; j++) {
            int col0 = (int)colB + wn * 32 + j * 8 + (lane & 3) * 2;
#pragma unroll
            for (int half = 0; half < 2; half++) {
                long r = r0e + half * 8;
                if (r >= R) continue;
#pragma unroll
                for (int cc = 0; cc < 2; cc++) {
                    int col = col0 + cc;
                    if (col >= M) continue;
                    float v = acc[mt][j][half * 2 + cc];
                    if (bias) v += __ldg(bias + col);
                    if (ACT) v = 0.5f * v * (1.0f + erff(v * 0.7071067811865475f));
                    if (MODE == 0) {
                        outF[r * (long)M + col] = v;
                    } else if (MODE == 1) {
                        split_write(v, &outS[r * (long)(2 * M) + col],
                                       &outS[r * (long)(2 * M) + M + col]);
                    } else {
                        if (col < 128)
                            split_write(v, &outS[r * 256 + col], &outS[r * 256 + 128 + col]);
                        else
                            outF[r * 64 + (col - 128)] = v;
                    }
                }
            }
        }
    }
}

// ---- GCN aggregate, ALL 4 SNAPSHOTS per block (shared edge list, MLP x4) ----
// grid = Nn; hW layout [si*Nn + row, 256]; out layout [si*Nn + node, 512] split.
__global__ void __launch_bounds__(256)
k_gcn_agg4(const float* __restrict__ hW,
           const float* __restrict__ bias, const float* __restrict__ g,
           const float* __restrict__ b, __nv_bfloat16* __restrict__ out) {
    const int t = blockIdx.x;
    const int d = threadIdx.x;
    float di = g_dinv[t];
    float di2 = di * di;

    float acc[Ss];
#pragma unroll
    for (int si = 0; si < Ss; si++)
        acc[si] = di2 * __ldg(&hW[((size_t)si * Nn + t) * Dd + d]);

    int e0 = g_rowp[t], e1 = g_rowp[t + 1];
#pragma unroll 2
    for (int e = e0; e < e1; e++) {
        int s = __ldg(&g_csrc[e]);
        float nm = __ldg(&g_cnorm[e]);
#pragma unroll
        for (int si = 0; si < Ss; si++)
            acc[si] += nm * __ldg(&hW[((size_t)si * Nn + s) * Dd + d]);
    }

    const float bd = bias[d], gd = g[d], bbd = b[d];
    __shared__ float red[16];
    __shared__ float mv[2];
    const int lane = d & 31, wid = d >> 5;

#pragma unroll
    for (int si = 0; si < Ss; si++) {
        float a = acc[si] + bd;
        float sum = a, sq = a * a;
#pragma unroll
        for (int o = 16; o; o >>= 1) {
            sum += __shfl_down_sync(0xffffffffu, sum, o);
            sq  += __shfl_down_sync(0xffffffffu, sq, o);
        }
        if (lane == 0) { red[wid] = sum; red[8 + wid] = sq; }
        __syncthreads();
        if (d == 0) {
            float s = 0.f, q = 0.f;
#pragma unroll
            for (int i = 0; i < 8; i++) { s += red[i]; q += red[8 + i]; }
            float m = s * (1.0f / 256.0f);
            float var = q * (1.0f / 256.0f) - m * m;
            mv[0] = m;
            mv[1] = rsqrtf(var + 1e-5f);
        }
        __syncthreads();
        float val = fmaxf((a - mv[0]) * mv[1] * gd + bbd, 0.0f);
        __nv_bfloat16* o = out + ((size_t)si * Nn + t) * 512;
        split_write(val, &o[d], &o[256 + d]);
    }
}

// ---------------- GRU cell, float4 vectorized ----------------
__global__ void k_gru_cell(const float* __restrict__ gi, const float* __restrict__ gh,
                           const float* __restrict__ bhh, const float* __restrict__ hprev,
                           float* __restrict__ hnew, __nv_bfloat16* __restrict__ hs,
                           int first) {
    int idx = blockIdx.x * blockDim.x + threadIdx.x;
    if (idx >= Nn * 64) return;
    int n = idx >> 6, d = (idx & 63) << 2;
    const float* gir = gi + (size_t)n * 768;
    float4 ir = *reinterpret_cast<const float4*>(gir + d);
    float4 iz = *reinterpret_cast<const float4*>(gir + 256 + d);
    float4 ig = *reinterpret_cast<const float4*>(gir + 512 + d);
    float4 hr, hz, hg, hp;
    if (first) {
        hr = *reinterpret_cast<const float4*>(bhh + d);
        hz = *reinterpret_cast<const float4*>(bhh + 256 + d);
        hg = *reinterpret_cast<const float4*>(bhh + 512 + d);
        hp = make_float4(0.f, 0.f, 0.f, 0.f);
    } else {
        const float* ghr = gh + (size_t)n * 768;
        hr = *reinterpret_cast<const float4*>(ghr + d);
        hz = *reinterpret_cast<const float4*>(ghr + 256 + d);
        hg = *reinterpret_cast<const float4*>(ghr + 512 + d);
        hp = *reinterpret_cast<const float4*>(hprev + (size_t)n * 256 + d);
    }
    float4 v;
#define GRU1(c) { \
        float r = 1.0f / (1.0f + expf(-(ir.c + hr.c))); \
        float z = 1.0f / (1.0f + expf(-(iz.c + hz.c))); \
        float ng = tanhf(ig.c + r * hg.c); \
        v.c = (1.0f - z) * ng + z * hp.c; }
    GRU1(x) GRU1(y) GRU1(z) GRU1(w)
#undef GRU1
    *reinterpret_cast<float4*>(hnew + (size_t)n * 256 + d) = v;
    split_write4(v, &hs[(size_t)n * 512 + d], &hs[(size_t)n * 512 + 256 + d]);
}

// ---------------- tiny head GEMM ----------------
__global__ void __launch_bounds__(256)
k_head5(const float* __restrict__ in, const float* __restrict__ W,
        const float* __restrict__ bias, float* __restrict__ out) {
    __shared__ float sW[5 * 64];
    for (int i = threadIdx.x; i < 5 * 64; i += blockDim.x) sW[i] = W[i];
    __syncthreads();
    int gw = (blockIdx.x * blockDim.x + threadIdx.x) >> 5;
    int lane = threadIdx.x & 31;
    if (gw >= Nn) return;
    float x0 = in[(size_t)gw * 64 + lane];
    float x1 = in[(size_t)gw * 64 + 32 + lane];
#pragma unroll
    for (int m = 0; m < 5; m++) {
        float p = x0 * sW[m * 64 + lane] + x1 * sW[m * 64 + 32 + lane];
#pragma unroll
        for (int o = 16; o; o >>= 1) p += __shfl_down_sync(0xffffffffu, p, o);
        if (lane == 0) out[(size_t)gw * 5 + m] = p + bias[m];
    }
}

// ---------------- host orchestration ----------------
template <typename T>
static T* symp(const void* sym) {
    void* p = nullptr;
    cudaGetSymbolAddress(&p, sym);
    return (T*)p;
}

extern "C" void kernel_launch(void* const* d_in, const int* in_sizes, int n_in,
                              void* d_out, int out_size) {
    const float* x    = (const float*)d_in[0];
    const int*   esrc = (const int*)d_in[1];
    const int*   edst = (const int*)d_in[2];
    const float* ew   = (const float*)d_in[3];
    const float* gcnW = (const float*)d_in[4];
    const float* gcnb = (const float*)d_in[5];
    const float* lng  = (const float*)d_in[6];
    const float* lnb  = (const float*)d_in[7];
    const float* Wih  = (const float*)d_in[8];
    const float* Whh  = (const float*)d_in[9];
    const float* bih  = (const float*)d_in[10];
    const float* bhh  = (const float*)d_in[11];
    const float* fc1W = (const float*)d_in[12];
    const float* fc1b = (const float*)d_in[13];
    const float* fc2W = (const float*)d_in[14];
    const float* fc2b = (const float*)d_in[15];
    const float* fc3W = (const float*)d_in[16];
    const float* fc3b = (const float*)d_in[17];
    const float* dh1W = (const float*)d_in[18];
    const float* dh1b = (const float*)d_in[19];
    const float* dh2W = (const float*)d_in[20];
    const float* dh2b = (const float*)d_in[21];

    float* outF = (float*)d_out;
    float* outD = outF + (size_t)Nn * Hh;

    float* tmpW  = symp<float>(g_tmpW);
    float* giAll = symp<float>(g_giAll);
    float* gh    = symp<float>(g_gh);
    float* h1    = symp<float>(g_h1);
    float* h2    = symp<float>(g_h2);
    float* f2    = symp<float>(g_f2);
    float* d1    = symp<float>(g_d1);
    float* cb    = symp<float>(g_cb);
    __nv_bfloat16* xs    = symp<__nv_bfloat16>(g_xs);
    __nv_bfloat16* aggA  = symp<__nv_bfloat16>(g_aggA);
    __nv_bfloat16* seqs  = symp<__nv_bfloat16>(g_seqs);
    __nv_bfloat16* hs    = symp<__nv_bfloat16>(g_hs);
    __nv_bfloat16* f1s   = symp<__nv_bfloat16>(g_f1s);
    __nv_bfloat16* gcnWs = symp<__nv_bfloat16>(g_gcnWs);
    __nv_bfloat16* Wihs  = symp<__nv_bfloat16>(g_Wihs);
    __nv_bfloat16* Whhs  = symp<__nv_bfloat16>(g_Whhs);
    __nv_bfloat16* cWs   = symp<__nv_bfloat16>(g_cWs);
    __nv_bfloat16* fc2Ws = symp<__nv_bfloat16>(g_fc2Ws);

    cudaFuncSetAttribute(gemm_mma, cudaFuncAttributeMaxDynamicSharedMemorySize, GEMM_SMEM);
    cudaFuncSetAttribute(gemm_mma, cudaFuncAttributePreferredSharedMemoryCarveout, 100);

    const int TB = 256;
    const int gN = (Nn + TB - 1) / TB;
    const int gE = (Ee + TB - 1) / TB;

    dim3 blk(256);
    const int RB4 = (SN + 127) / 128;   // 625
    const int RB1 = (Nn + 127) / 128;   // 157
    dim3 gGCN(2, RB4);
    dim3 gGI(6, RB4);
    dim3 gGRU(6, RB1);
    dim3 gHC(2, RB1);
    dim3 gH1(1, RB1);

    // ---- prologue ordered so the big GCN GEMM stays at launch slot #4 (ncu -s 5) ----
    k_splitT<<<(256 * 256 + TB - 1) / TB, TB>>>(gcnW, gcnWs, 256, 256);                 // #1
    k_split<<<((long)SN * 64 + TB - 1) / TB, TB>>>(x, xs, (long)SN * 64, 64);           // #2
    k_splitT<<<(256 * 256 + TB - 1) / TB, TB>>>(gcnW + 256 * 256,
                                                gcnWs + 256 * 512, 256, 256);           // #3
    gemm_mma<<<gGCN, blk, GEMM_SMEM>>>(xs, gcnWs, nullptr, tmpW, nullptr,
                                       SN, 256, 256, 0, 0);                             // #4 <- profile
    k_splitT<<<(256 * 256 + TB - 1) / TB, TB>>>(gcnW + 2 * 256 * 256,
                                                gcnWs + 2 * 256 * 512, 256, 256);
    k_split<<<(768 * 64 + TB - 1) / TB, TB>>>(Wih,  Wihs,  (long)768 * 64, 64);
    k_split<<<(768 * 64 + TB - 1) / TB, TB>>>(Whh,  Whhs,  (long)768 * 64, 64);
    k_split<<<(128 * 64 + TB - 1) / TB, TB>>>(fc1W, cWs, (long)128 * 64, 64);
    k_split<<<(64 * 64 + TB - 1) / TB, TB>>>(dh1W, cWs + (size_t)128 * 512, (long)64 * 64, 64);
    k_split<<<(64 * 32 + TB - 1) / TB, TB>>>(fc2W, fc2Ws, (long)64 * 32, 32);
    cudaMemcpyAsync(cb, fc1b, 128 * sizeof(float), cudaMemcpyDeviceToDevice);
    cudaMemcpyAsync(cb + 128, dh1b, 64 * sizeof(float), cudaMemcpyDeviceToDevice);

    // graph preprocessing -> CSR
    k_init_deg_cnt<<<gN, TB>>>();
    k_edge_deg_cnt<<<gE, TB>>>(edst, ew);
    k_dinv<<<gN, TB>>>();
    k_scan1<<<NB, 256>>>();
    k_scan2<<<1, 128>>>();
    k_scan3<<<NB, 256>>>();
    k_fill_csr<<<gE, TB>>>(esrc, edst, ew);

    // batched GCN stack: aggregation fuses ALL 4 snapshots per block
    k_gcn_agg4<<<Nn, 256>>>(tmpW, gcnb + 0 * Dd, lng + 0 * Dd, lnb + 0 * Dd, aggA);
    gemm_mma<<<gGCN, blk, GEMM_SMEM>>>(aggA, gcnWs + 1 * 256 * 512, nullptr, tmpW, nullptr,
                                       SN, 256, 256, 0, 0);
    k_gcn_agg4<<<Nn, 256>>>(tmpW, gcnb + 1 * Dd, lng + 1 * Dd, lnb + 1 * Dd, aggA);
    gemm_mma<<<gGCN, blk, GEMM_SMEM>>>(aggA, gcnWs + 2 * 256 * 512, nullptr, tmpW, nullptr,
                                       SN, 256, 256, 0, 0);
    k_gcn_agg4<<<Nn, 256>>>(tmpW, gcnb + 2 * Dd, lng + 2 * Dd, lnb + 2 * Dd, seqs);

    // gi for ALL timesteps in one GEMM
    gemm_mma<<<gGI, blk, GEMM_SMEM>>>(seqs, Wihs, bih, giAll, nullptr, SN, 768, 256, 0, 0);

    // GRU recurrence
    const int gCell = (Nn * 64 + TB - 1) / TB;
    k_gru_cell<<<gCell, TB>>>(giAll, gh, bhh, h1, h1, hs, 1);
    for (int t = 1; t < Ss; t++) {
        float* hp = (t & 1) ? h1 : h2;
        float* hn = (t & 1) ? h2 : h1;
        gemm_mma<<<gGRU, blk, GEMM_SMEM>>>(hs, Whhs, bhh, gh, nullptr, Nn, 768, 256, 0, 0);
        k_gru_cell<<<gCell, TB>>>(giAll + (size_t)t * Nn * 768, gh, bhh, hp, hn, hs, 0);
    }

    // fused fc1|dh1 GEMM (M=192)
    gemm_mma<<<gHC, blk, GEMM_SMEM>>>(hs, cWs, cb, d1, f1s, Nn, 192, 256, 1, 3);
    gemm_mma<<<gH1, blk, GEMM_SMEM>>>(f1s, fc2Ws, fc2b, f2, nullptr, Nn, 64, 128, 1, 0);
    k_head5<<<(Nn * 32 + TB - 1) / TB, TB>>>(f2, fc3W, fc3b, outF);
    k_head5<<<(Nn * 32 + TB - 1) / TB, TB>>>(d1, dh2W, dh2b, outD);
}

// round 13
// speedup vs baseline: 2.5958x; 1.1250x over previous
#include <cuda_runtime.h>
#include <cuda_bf16.h>
#include <math.h>
#include <stdint.h>

#define Nn 20000
#define Dd 256
#define Ss 4
#define Ee 320000
#define Hh 5
#define SN (Ss * Nn)
#define NB 79                      // ceil(Nn/256)

// ---------------- scratch (device globals; no allocs allowed) ----------------
__device__ float g_deg[Nn];
__device__ float g_dinv[Nn];
__device__ int   g_cnt[Nn];
__device__ int   g_rowp[Nn + 1];
__device__ int   g_fill[Nn];
__device__ int   g_bsum[NB + 1];
__device__ int   g_boff[NB + 1];
__device__ int   g_csrc[Ee];
__device__ float g_cnorm[Ee];

__device__ float g_tmpW[SN * Dd];
__device__ float g_giAll[SN * 3 * Dd];
__device__ float g_gh[Nn * 3 * Dd];
__device__ float g_h1[Nn * Dd];
__device__ float g_h2[Nn * Dd];
__device__ float g_f2[Nn * 64];
__device__ float g_d1[Nn * 64];
__device__ float g_cb[192];

// split-bf16 activations: layout [rows, 2K] = [hi | lo]
__device__ __nv_bfloat16 g_xs[SN * 512];
__device__ __nv_bfloat16 g_aggA[SN * 512];
__device__ __nv_bfloat16 g_seqs[SN * 512];
__device__ __nv_bfloat16 g_hs[Nn * 512];
__device__ __nv_bfloat16 g_f1s[Nn * 256];

// split-bf16 weights: [M, 2K]
__device__ __nv_bfloat16 g_gcnWs[3 * 256 * 512];
__device__ __nv_bfloat16 g_Wihs[768 * 512];
__device__ __nv_bfloat16 g_Whhs[768 * 512];
__device__ __nv_bfloat16 g_cWs[192 * 512];
__device__ __nv_bfloat16 g_fc2Ws[64 * 256];

// ---------------- helpers ----------------
__device__ __forceinline__ void split_write(float v, __nv_bfloat16* hi, __nv_bfloat16* lo) {
    __nv_bfloat16 h = __float2bfloat16(v);
    *hi = h;
    *lo = __float2bfloat16(v - __bfloat162float(h));
}
__device__ __forceinline__ void split_write2(float v0, float v1,
                                             __nv_bfloat16* hi, __nv_bfloat16* lo) {
    __nv_bfloat16 h0 = __float2bfloat16(v0), h1 = __float2bfloat16(v1);
    __nv_bfloat162 hh; hh.x = h0; hh.y = h1;
    *reinterpret_cast<__nv_bfloat162*>(hi) = hh;
    __nv_bfloat162 ll;
    ll.x = __float2bfloat16(v0 - __bfloat162float(h0));
    ll.y = __float2bfloat16(v1 - __bfloat162float(h1));
    *reinterpret_cast<__nv_bfloat162*>(lo) = ll;
}
__device__ __forceinline__ void split_write4(float4 v, __nv_bfloat16* hi, __nv_bfloat16* lo) {
    split_write2(v.x, v.y, hi, lo);
    split_write2(v.z, v.w, hi + 2, lo + 2);
}
__device__ __forceinline__ void ldsm4(uint32_t* r, uint32_t addr) {
    asm volatile("ldmatrix.sync.aligned.m8n8.x4.shared.b16 {%0,%1,%2,%3}, [%4];"
                 : "=r"(r[0]), "=r"(r[1]), "=r"(r[2]), "=r"(r[3]) : "r"(addr));
}
__device__ __forceinline__ void mma16816(float* c, const uint32_t* a, const uint32_t* b) {
    asm volatile(
        "mma.sync.aligned.m16n8k16.row.col.f32.bf16.bf16.f32 "
        "{%0,%1,%2,%3}, {%4,%5,%6,%7}, {%8,%9}, {%0,%1,%2,%3};"
        : "+f"(c[0]), "+f"(c[1]), "+f"(c[2]), "+f"(c[3])
        : "r"(a[0]), "r"(a[1]), "r"(a[2]), "r"(a[3]), "r"(b[0]), "r"(b[1]));
}
__device__ __forceinline__ void cpa16z(uint32_t dst, const void* src, int sz) {
    asm volatile("cp.async.cg.shared.global [%0], [%1], 16, %2;"
                 :: "r"(dst), "l"(src), "r"(sz));
}
__device__ __forceinline__ float gelu1(float v) {
    return 0.5f * v * (1.0f + erff(v * 0.7071067811865475f));
}

// ---------------- graph preprocessing ----------------
__global__ void k_init_deg_cnt() {
    int i = blockIdx.x * blockDim.x + threadIdx.x;
    if (i < Nn) { g_deg[i] = 1.0f; g_cnt[i] = 0; }
}
__global__ void k_edge_deg_cnt(const int* __restrict__ dst, const float* __restrict__ w) {
    int e = blockIdx.x * blockDim.x + threadIdx.x;
    if (e < Ee) {
        int t = dst[e];
        atomicAdd(&g_deg[t], w[e]);
        atomicAdd(&g_cnt[t], 1);
    }
}
__global__ void k_dinv() {
    int i = blockIdx.x * blockDim.x + threadIdx.x;
    if (i < Nn) g_dinv[i] = rsqrtf(g_deg[i]);
}
__global__ void __launch_bounds__(256) k_scan1() {
    __shared__ int wsum[8];
    int i = blockIdx.x * 256 + threadIdx.x;
    int lane = threadIdx.x & 31, wd = threadIdx.x >> 5;
    int v = (i < Nn) ? g_cnt[i] : 0;
    int x = v;
#pragma unroll
    for (int o = 1; o < 32; o <<= 1) {
        int y = __shfl_up_sync(0xffffffffu, x, o);
        if (lane >= o) x += y;
    }
    if (lane == 31) wsum[wd] = x;
    __syncthreads();
    if (threadIdx.x == 0) {
        int acc = 0;
#pragma unroll
        for (int w = 0; w < 8; w++) { int t = wsum[w]; wsum[w] = acc; acc += t; }
        g_bsum[blockIdx.x] = acc;
    }
    __syncthreads();
    if (i < Nn) g_rowp[i] = wsum[wd] + x - v;
}
__global__ void k_scan2() {
    int t = threadIdx.x;
    __shared__ int sh[NB];
    if (t < NB) sh[t] = g_bsum[t];
    __syncthreads();
    if (t == 0) {
        int acc = 0;
        for (int b = 0; b < NB; b++) { int v = sh[b]; g_boff[b] = acc; acc += v; }
        g_rowp[Nn] = acc;
    }
}
__global__ void __launch_bounds__(256) k_scan3() {
    int i = blockIdx.x * 256 + threadIdx.x;
    if (i < Nn) {
        int r = g_rowp[i] + g_boff[blockIdx.x];
        g_rowp[i] = r;
        g_fill[i] = r;
    }
}
__global__ void k_fill_csr(const int* __restrict__ src, const int* __restrict__ dst,
                           const float* __restrict__ w) {
    int e = blockIdx.x * blockDim.x + threadIdx.x;
    if (e < Ee) {
        int s = src[e], t = dst[e];
        int pos = atomicAdd(&g_fill[t], 1);
        g_csrc[pos]  = s;
        g_cnorm[pos] = g_dinv[s] * w[e] * g_dinv[t];
    }
}

// ---------------- split conversion kernels ----------------
__global__ void k_split(const float* __restrict__ in, __nv_bfloat16* __restrict__ out,
                        long total4, int K4) {
    long idx = (long)blockIdx.x * blockDim.x + threadIdx.x;
    if (idx >= total4) return;
    long r = idx / K4;
    int  c = (int)(idx - r * K4) * 4;
    int  K = K4 * 4;
    float4 v = *reinterpret_cast<const float4*>(in + r * K + c);
    split_write4(v, &out[r * 2 * K + c], &out[r * 2 * K + K + c]);
}
__global__ void k_splitT(const float* __restrict__ in, __nv_bfloat16* __restrict__ out,
                         int Kd, int Md) {
    long idx = (long)blockIdx.x * blockDim.x + threadIdx.x;
    if (idx >= (long)Kd * Md) return;
    int k = (int)(idx / Md);
    int m = (int)(idx - (long)k * Md);
    float v = in[idx];
    split_write(v, &out[(long)m * 2 * Kd + k], &out[(long)m * 2 * Kd + Kd + k]);
}

// ---------------- bf16 mma.sync GEMM, merged split, hoisted loader ----------------
// C[R,M] = A[R,K] @ B[M,K]^T; A/B split: [rows, 2K] = [hi | lo].
// Loader: thread -> (array, row0=8-row span, seg). One base ptr/thread; per chunk
// just 8 offset adds + 8 cp.async. MODE 0: fp32 outF. MODE 3: fused fc1|dh1.
#define SROW2 40
#define ARR_B (128 * SROW2 * 2)
#define STAGE_B (4 * ARR_B)
#define GEMM_SMEM (2 * STAGE_B)
template <int ACT, int MODE>
__global__ void __launch_bounds__(256, 2)
gemm_mma(const __nv_bfloat16* __restrict__ A, const __nv_bfloat16* __restrict__ B,
         const float* __restrict__ bias, float* __restrict__ outF,
         __nv_bfloat16* __restrict__ outS, int R, int M, int K) {
    extern __shared__ __align__(16) __nv_bfloat16 smg[];
    const uint32_t sbase = (uint32_t)__cvta_generic_to_shared(smg);

    const int tid  = threadIdx.x;
    const int lane = tid & 31, wid = tid >> 5;
    const int wm = wid & 1;
    const int wn = wid >> 1;
    const long rowA = (long)blockIdx.y * 128;
    const long colB = (long)blockIdx.x * 128;
    const int K2 = 2 * K;
    const int NC = K >> 5;

    // ---- hoisted loader state: arr = tid>>6 (0=Ah 1=Al 2=Bh 3=Bl) ----
    const int arrid = tid >> 6;
    const int l6    = tid & 63;
    const int row0  = (l6 >> 2) * 8;     // 8 consecutive rows per thread
    const int seg   = l6 & 3;
    const bool isA  = arrid < 2;
    const long rb   = (isA ? rowA : colB) + row0;
    const int  lim  = isA ? R : M;
    int szs[8];
#pragma unroll
    for (int u = 0; u < 8; u++) szs[u] = (rb + u < lim) ? 16 : 0;
    const __nv_bfloat16* sp = (isA ? A : B) + rb * (long)K2 +
                              ((arrid & 1) ? K : 0) + seg * 8;
    const uint32_t dstb = (uint32_t)arrid * ARR_B +
                          (uint32_t)(row0 * SROW2 + seg * 8) * 2;

    float acc[4][4][4];
#pragma unroll
    for (int i = 0; i < 4; i++)
#pragma unroll
        for (int j = 0; j < 4; j++)
#pragma unroll
            for (int k = 0; k < 4; k++) acc[i][j][k] = 0.0f;

    auto ld_chunk = [&](int c, int buf) {
        uint32_t stg = sbase + (uint32_t)buf * STAGE_B + dstb;
        const __nv_bfloat16* s = sp + (long)c * 32;
#pragma unroll
        for (int u = 0; u < 8; u++)
            cpa16z(stg + (uint32_t)(u * SROW2 * 2), s + (long)u * K2, szs[u]);
        asm volatile("cp.async.commit_group;" ::: "memory");
    };

    ld_chunk(0, 0);

    const uint32_t aOffC = ((uint32_t)(wm * 64 + (lane & 15)) * SROW2 + (lane >> 4) * 8) * 2;
    const uint32_t bOffC = ((uint32_t)(wn * 32 + ((lane >> 4) & 1) * 8 + (lane & 7)) * SROW2 +
                            ((lane >> 3) & 1) * 8) * 2;

    for (int c = 0; c < NC; c++) {
        int buf = c & 1;
        if (c + 1 < NC) {
            ld_chunk(c + 1, buf ^ 1);
            asm volatile("cp.async.wait_group 1;" ::: "memory");
        } else {
            asm volatile("cp.async.wait_group 0;" ::: "memory");
        }
        __syncthreads();
        uint32_t stg = sbase + (uint32_t)buf * STAGE_B;
        uint32_t ah = stg + aOffC;
        uint32_t al = ah + ARR_B;
        uint32_t bh = stg + 2 * ARR_B + bOffC;
        uint32_t bl = bh + ARR_B;
#pragma unroll
        for (int ks = 0; ks < 2; ks++) {
            uint32_t koff = (uint32_t)(ks * 16) * 2;
            uint32_t bhf[2][4], blf[2][4];
#pragma unroll
            for (int nt = 0; nt < 2; nt++) {
                ldsm4(bhf[nt], bh + (uint32_t)(nt * 16 * SROW2) * 2 + koff);
                ldsm4(blf[nt], bl + (uint32_t)(nt * 16 * SROW2) * 2 + koff);
            }
#pragma unroll
            for (int half = 0; half < 2; half++) {
                uint32_t ahf[2][4], alf[2][4];
#pragma unroll
                for (int m2 = 0; m2 < 2; m2++) {
                    int mt = half * 2 + m2;
                    ldsm4(ahf[m2], ah + (uint32_t)(mt * 16 * SROW2) * 2 + koff);
                    ldsm4(alf[m2], al + (uint32_t)(mt * 16 * SROW2) * 2 + koff);
                }
#pragma unroll
                for (int m2 = 0; m2 < 2; m2++)
#pragma unroll
                    for (int j = 0; j < 4; j++)
                        mma16816(acc[half * 2 + m2][j], ahf[m2], &bhf[j >> 1][(j & 1) * 2]);
#pragma unroll
                for (int m2 = 0; m2 < 2; m2++)
#pragma unroll
                    for (int j = 0; j < 4; j++)
                        mma16816(acc[half * 2 + m2][j], ahf[m2], &blf[j >> 1][(j & 1) * 2]);
#pragma unroll
                for (int m2 = 0; m2 < 2; m2++)
#pragma unroll
                    for (int j = 0; j < 4; j++)
                        mma16816(acc[half * 2 + m2][j], alf[m2], &bhf[j >> 1][(j & 1) * 2]);
            }
        }
        __syncthreads();
    }

    // vectorized epilogue (pair-wise stores; cols even-aligned, M even)
#pragma unroll
    for (int mt = 0; mt < 4; mt++) {
        long r0e = rowA + wm * 64 + mt * 16 + (lane >> 2);
#pragma unroll
        for (int j = 0; j < 4; j++) {
            int col0 = (int)colB + wn * 32 + j * 8 + (lane & 3) * 2;
            if (col0 >= M) continue;
            float2 b2 = make_float2(0.f, 0.f);
            if (bias) b2 = *reinterpret_cast<const float2*>(bias + col0);
#pragma unroll
            for (int half = 0; half < 2; half++) {
                long r = r0e + half * 8;
                if (r >= R) continue;
                float v0 = acc[mt][j][half * 2 + 0] + b2.x;
                float v1 = acc[mt][j][half * 2 + 1] + b2.y;
                if (ACT) { v0 = gelu1(v0); v1 = gelu1(v1); }
                if (MODE == 0) {
                    *reinterpret_cast<float2*>(outF + r * (long)M + col0) = make_float2(v0, v1);
                } else {   // MODE 3: fused fc1|dh1
                    if (col0 < 128)
                        split_write2(v0, v1, &outS[r * 256 + col0], &outS[r * 256 + 128 + col0]);
                    else
                        *reinterpret_cast<float2*>(outF + r * 64 + (col0 - 128)) =
                            make_float2(v0, v1);
                }
            }
        }
    }
}

// ---- GCN aggregate, ALL 4 SNAPSHOTS per block, joint LN reduction ----
__global__ void __launch_bounds__(256)
k_gcn_agg4(const float* __restrict__ hW,
           const float* __restrict__ bias, const float* __restrict__ g,
           const float* __restrict__ b, __nv_bfloat16* __restrict__ out) {
    const int t = blockIdx.x;
    const int d = threadIdx.x;
    float di = g_dinv[t];
    float di2 = di * di;

    float acc[Ss];
#pragma unroll
    for (int si = 0; si < Ss; si++)
        acc[si] = di2 * __ldg(&hW[((size_t)si * Nn + t) * Dd + d]);

    int e0 = g_rowp[t], e1 = g_rowp[t + 1];
#pragma unroll 2
    for (int e = e0; e < e1; e++) {
        int s = __ldg(&g_csrc[e]);
        float nm = __ldg(&g_cnorm[e]);
#pragma unroll
        for (int si = 0; si < Ss; si++)
            acc[si] += nm * __ldg(&hW[((size_t)si * Nn + s) * Dd + d]);
    }

    const float bd = bias[d], gd = g[d], bbd = b[d];
    __shared__ float redS[Ss][8], redQ[Ss][8];
    __shared__ float mvm[Ss], mvr[Ss];
    const int lane = d & 31, wid = d >> 5;

    float a[Ss], s[Ss], q[Ss];
#pragma unroll
    for (int si = 0; si < Ss; si++) {
        a[si] = acc[si] + bd;
        s[si] = a[si];
        q[si] = a[si] * a[si];
    }
#pragma unroll
    for (int o = 16; o; o >>= 1) {
#pragma unroll
        for (int si = 0; si < Ss; si++) {
            s[si] += __shfl_down_sync(0xffffffffu, s[si], o);
            q[si] += __shfl_down_sync(0xffffffffu, q[si], o);
        }
    }
    if (lane == 0) {
#pragma unroll
        for (int si = 0; si < Ss; si++) { redS[si][wid] = s[si]; redQ[si][wid] = q[si]; }
    }
    __syncthreads();
    if (d < Ss) {
        float ss = 0.f, qq = 0.f;
#pragma unroll
        for (int i = 0; i < 8; i++) { ss += redS[d][i]; qq += redQ[d][i]; }
        float m = ss * (1.0f / 256.0f);
        float var = qq * (1.0f / 256.0f) - m * m;
        mvm[d] = m;
        mvr[d] = rsqrtf(var + 1e-5f);
    }
    __syncthreads();
#pragma unroll
    for (int si = 0; si < Ss; si++) {
        float val = fmaxf((a[si] - mvm[si]) * mvr[si] * gd + bbd, 0.0f);
        __nv_bfloat16* o = out + ((size_t)si * Nn + t) * 512;
        split_write(val, &o[d], &o[256 + d]);
    }
}

// ---------------- GRU cell, float4 vectorized ----------------
__global__ void k_gru_cell(const float* __restrict__ gi, const float* __restrict__ gh,
                           const float* __restrict__ bhh, const float* __restrict__ hprev,
                           float* __restrict__ hnew, __nv_bfloat16* __restrict__ hs,
                           int first) {
    int idx = blockIdx.x * blockDim.x + threadIdx.x;
    if (idx >= Nn * 64) return;
    int n = idx >> 6, d = (idx & 63) << 2;
    const float* gir = gi + (size_t)n * 768;
    float4 ir = *reinterpret_cast<const float4*>(gir + d);
    float4 iz = *reinterpret_cast<const float4*>(gir + 256 + d);
    float4 ig = *reinterpret_cast<const float4*>(gir + 512 + d);
    float4 hr, hz, hg, hp;
    if (first) {
        hr = *reinterpret_cast<const float4*>(bhh + d);
        hz = *reinterpret_cast<const float4*>(bhh + 256 + d);
        hg = *reinterpret_cast<const float4*>(bhh + 512 + d);
        hp = make_float4(0.f, 0.f, 0.f, 0.f);
    } else {
        const float* ghr = gh + (size_t)n * 768;
        hr = *reinterpret_cast<const float4*>(ghr + d);
        hz = *reinterpret_cast<const float4*>(ghr + 256 + d);
        hg = *reinterpret_cast<const float4*>(ghr + 512 + d);
        hp = *reinterpret_cast<const float4*>(hprev + (size_t)n * 256 + d);
    }
    float4 v;
#define GRU1(c) { \
        float r = 1.0f / (1.0f + expf(-(ir.c + hr.c))); \
        float z = 1.0f / (1.0f + expf(-(iz.c + hz.c))); \
        float ng = tanhf(ig.c + r * hg.c); \
        v.c = (1.0f - z) * ng + z * hp.c; }
    GRU1(x) GRU1(y) GRU1(z) GRU1(w)
#undef GRU1
    *reinterpret_cast<float4*>(hnew + (size_t)n * 256 + d) = v;
    split_write4(v, &hs[(size_t)n * 512 + d], &hs[(size_t)n * 512 + 256 + d]);
}

// ---------------- tiny head GEMM ----------------
__global__ void __launch_bounds__(256)
k_head5(const float* __restrict__ in, const float* __restrict__ W,
        const float* __restrict__ bias, float* __restrict__ out) {
    __shared__ float sW[5 * 64];
    for (int i = threadIdx.x; i < 5 * 64; i += blockDim.x) sW[i] = W[i];
    __syncthreads();
    int gw = (blockIdx.x * blockDim.x + threadIdx.x) >> 5;
    int lane = threadIdx.x & 31;
    if (gw >= Nn) return;
    float x0 = in[(size_t)gw * 64 + lane];
    float x1 = in[(size_t)gw * 64 + 32 + lane];
#pragma unroll
    for (int m = 0; m < 5; m++) {
        float p = x0 * sW[m * 64 + lane] + x1 * sW[m * 64 + 32 + lane];
#pragma unroll
        for (int o = 16; o; o >>= 1) p += __shfl_down_sync(0xffffffffu, p, o);
        if (lane == 0) out[(size_t)gw * 5 + m] = p + bias[m];
    }
}

// ---------------- host orchestration ----------------
template <typename T>
static T* symp(const void* sym) {
    void* p = nullptr;
    cudaGetSymbolAddress(&p, sym);
    return (T*)p;
}

extern "C" void kernel_launch(void* const* d_in, const int* in_sizes, int n_in,
                              void* d_out, int out_size) {
    const float* x    = (const float*)d_in[0];
    const int*   esrc = (const int*)d_in[1];
    const int*   edst = (const int*)d_in[2];
    const float* ew   = (const float*)d_in[3];
    const float* gcnW = (const float*)d_in[4];
    const float* gcnb = (const float*)d_in[5];
    const float* lng  = (const float*)d_in[6];
    const float* lnb  = (const float*)d_in[7];
    const float* Wih  = (const float*)d_in[8];
    const float* Whh  = (const float*)d_in[9];
    const float* bih  = (const float*)d_in[10];
    const float* bhh  = (const float*)d_in[11];
    const float* fc1W = (const float*)d_in[12];
    const float* fc1b = (const float*)d_in[13];
    const float* fc2W = (const float*)d_in[14];
    const float* fc2b = (const float*)d_in[15];
    const float* fc3W = (const float*)d_in[16];
    const float* fc3b = (const float*)d_in[17];
    const float* dh1W = (const float*)d_in[18];
    const float* dh1b = (const float*)d_in[19];
    const float* dh2W = (const float*)d_in[20];
    const float* dh2b = (const float*)d_in[21];

    float* outF = (float*)d_out;
    float* outD = outF + (size_t)Nn * Hh;

    float* tmpW  = symp<float>(g_tmpW);
    float* giAll = symp<float>(g_giAll);
    float* gh    = symp<float>(g_gh);
    float* h1    = symp<float>(g_h1);
    float* h2    = symp<float>(g_h2);
    float* f2    = symp<float>(g_f2);
    float* d1    = symp<float>(g_d1);
    float* cb    = symp<float>(g_cb);
    __nv_bfloat16* xs    = symp<__nv_bfloat16>(g_xs);
    __nv_bfloat16* aggA  = symp<__nv_bfloat16>(g_aggA);
    __nv_bfloat16* seqs  = symp<__nv_bfloat16>(g_seqs);
    __nv_bfloat16* hs    = symp<__nv_bfloat16>(g_hs);
    __nv_bfloat16* f1s   = symp<__nv_bfloat16>(g_f1s);
    __nv_bfloat16* gcnWs = symp<__nv_bfloat16>(g_gcnWs);
    __nv_bfloat16* Wihs  = symp<__nv_bfloat16>(g_Wihs);
    __nv_bfloat16* Whhs  = symp<__nv_bfloat16>(g_Whhs);
    __nv_bfloat16* cWs   = symp<__nv_bfloat16>(g_cWs);
    __nv_bfloat16* fc2Ws = symp<__nv_bfloat16>(g_fc2Ws);

    cudaFuncSetAttribute(gemm_mma<0, 0>, cudaFuncAttributeMaxDynamicSharedMemorySize, GEMM_SMEM);
    cudaFuncSetAttribute(gemm_mma<0, 0>, cudaFuncAttributePreferredSharedMemoryCarveout, 100);
    cudaFuncSetAttribute(gemm_mma<1, 0>, cudaFuncAttributeMaxDynamicSharedMemorySize, GEMM_SMEM);
    cudaFuncSetAttribute(gemm_mma<1, 0>, cudaFuncAttributePreferredSharedMemoryCarveout, 100);
    cudaFuncSetAttribute(gemm_mma<1, 3>, cudaFuncAttributeMaxDynamicSharedMemorySize, GEMM_SMEM);
    cudaFuncSetAttribute(gemm_mma<1, 3>, cudaFuncAttributePreferredSharedMemoryCarveout, 100);

    const int TB = 256;
    const int gN = (Nn + TB - 1) / TB;
    const int gE = (Ee + TB - 1) / TB;

    dim3 blk(256);
    const int RB4 = (SN + 127) / 128;   // 625
    const int RB1 = (Nn + 127) / 128;   // 157
    dim3 gGCN(2, RB4);
    dim3 gGI(6, RB4);
    dim3 gGRU(6, RB1);
    dim3 gHC(2, RB1);
    dim3 gH1(1, RB1);

    // ---- prologue ordered so the big GCN GEMM stays at launch slot #4 (ncu -s 5) ----
    k_splitT<<<(256 * 256 + TB - 1) / TB, TB>>>(gcnW, gcnWs, 256, 256);                 // #1
    k_split<<<((long)SN * 64 + TB - 1) / TB, TB>>>(x, xs, (long)SN * 64, 64);           // #2
    k_splitT<<<(256 * 256 + TB - 1) / TB, TB>>>(gcnW + 256 * 256,
                                                gcnWs + 256 * 512, 256, 256);           // #3
    gemm_mma<0, 0><<<gGCN, blk, GEMM_SMEM>>>(xs, gcnWs, nullptr, tmpW, nullptr,
                                             SN, 256, 256);                             // #4 <- profile
    k_splitT<<<(256 * 256 + TB - 1) / TB, TB>>>(gcnW + 2 * 256 * 256,
                                                gcnWs + 2 * 256 * 512, 256, 256);
    k_split<<<(768 * 64 + TB - 1) / TB, TB>>>(Wih,  Wihs,  (long)768 * 64, 64);
    k_split<<<(768 * 64 + TB - 1) / TB, TB>>>(Whh,  Whhs,  (long)768 * 64, 64);
    k_split<<<(128 * 64 + TB - 1) / TB, TB>>>(fc1W, cWs, (long)128 * 64, 64);
    k_split<<<(64 * 64 + TB - 1) / TB, TB>>>(dh1W, cWs + (size_t)128 * 512, (long)64 * 64, 64);
    k_split<<<(64 * 32 + TB - 1) / TB, TB>>>(fc2W, fc2Ws, (long)64 * 32, 32);
    cudaMemcpyAsync(cb, fc1b, 128 * sizeof(float), cudaMemcpyDeviceToDevice);
    cudaMemcpyAsync(cb + 128, dh1b, 64 * sizeof(float), cudaMemcpyDeviceToDevice);

    // graph preprocessing -> CSR
    k_init_deg_cnt<<<gN, TB>>>();
    k_edge_deg_cnt<<<gE, TB>>>(edst, ew);
    k_dinv<<<gN, TB>>>();
    k_scan1<<<NB, 256>>>();
    k_scan2<<<1, 128>>>();
    k_scan3<<<NB, 256>>>();
    k_fill_csr<<<gE, TB>>>(esrc, edst, ew);

    // batched GCN stack: aggregation fuses ALL 4 snapshots per block
    k_gcn_agg4<<<Nn, 256>>>(tmpW, gcnb + 0 * Dd, lng + 0 * Dd, lnb + 0 * Dd, aggA);
    gemm_mma<0, 0><<<gGCN, blk, GEMM_SMEM>>>(aggA, gcnWs + 1 * 256 * 512, nullptr, tmpW,
                                             nullptr, SN, 256, 256);
    k_gcn_agg4<<<Nn, 256>>>(tmpW, gcnb + 1 * Dd, lng + 1 * Dd, lnb + 1 * Dd, aggA);
    gemm_mma<0, 0><<<gGCN, blk, GEMM_SMEM>>>(aggA, gcnWs + 2 * 256 * 512, nullptr, tmpW,
                                             nullptr, SN, 256, 256);
    k_gcn_agg4<<<Nn, 256>>>(tmpW, gcnb + 2 * Dd, lng + 2 * Dd, lnb + 2 * Dd, seqs);

    // gi for ALL timesteps in one GEMM
    gemm_mma<0, 0><<<gGI, blk, GEMM_SMEM>>>(seqs, Wihs, bih, giAll, nullptr, SN, 768, 256);

    // GRU recurrence
    const int gCell = (Nn * 64 + TB - 1) / TB;
    k_gru_cell<<<gCell, TB>>>(giAll, gh, bhh, h1, h1, hs, 1);
    for (int t = 1; t < Ss; t++) {
        float* hp = (t & 1) ? h1 : h2;
        float* hn = (t & 1) ? h2 : h1;
        gemm_mma<0, 0><<<gGRU, blk, GEMM_SMEM>>>(hs, Whhs, bhh, gh, nullptr, Nn, 768, 256);
        k_gru_cell<<<gCell, TB>>>(giAll + (size_t)t * Nn * 768, gh, bhh, hp, hn, hs, 0);
    }

    // fused fc1|dh1 GEMM (M=192)
    gemm_mma<1, 3><<<gHC, blk, GEMM_SMEM>>>(hs, cWs, cb, d1, f1s, Nn, 192, 256);
    gemm_mma<1, 0><<<gH1, blk, GEMM_SMEM>>>(f1s, fc2Ws, fc2b, f2, nullptr, Nn, 64, 128);
    k_head5<<<(Nn * 32 + TB - 1) / TB, TB>>>(f2, fc3W, fc3b, outF);
    k_head5<<<(Nn * 32 + TB - 1) / TB, TB>>>(d1, dh2W, dh2b, outD);
}